// round 1
// baseline (speedup 1.0000x reference)
#include <cuda_runtime.h>
#include <cuda_bf16.h>

// SVC8 5x5: out[b,co,oh,ow] = bias[i,co] + sum_{ci,kh,kw} x[b,ci,oh+kh-2,ow+kw-2] * w[i,co,ci,kh,kw]
// where i = 2*(oh%4) + (ow%2), zero padding outside.
//
// Strategy: f32x2 packed FMA (SASS FFMA2). Each thread: fixed (b, co, oh),
// 32 consecutive output columns as 16 f32x2 accumulators. Even/odd lane of a
// pair uses conv 2r / 2r+1 -> weight operand is a prepacked (w_even,w_odd)
// pair; input operand is an adjacent input pair, loaded via LDS.64 from two
// shared-memory copies (second copy shifted by one float so odd-offset pairs
// are 8B aligned).

typedef unsigned long long ull;

__device__ __forceinline__ void fma2(ull& d, ull a, ull b) {
    asm("fma.rn.f32x2 %0, %1, %2, %0;" : "+l"(d) : "l"(a), "l"(b));
}

// smem layout (dynamic, 57600 B):
//   [0,      38400)  ull   wpk[4][16][75]  packed (w_even, w_odd) pairs
//   [38400,  48000)  float sEf[3][20][40]  input tile, cols OW0-2 .. OW0+33 (36 used)
//   [48000,  57600)  float sOf[3][20][40]  same shifted by +1 col (34 used)
#define SMEM_BYTES 57600

__global__ void __launch_bounds__(256) svc8_kernel(
    const float* __restrict__ x,
    const float* __restrict__ w,
    const float* __restrict__ bias,
    float* __restrict__ out)
{
    constexpr int H = 720, W = 1280, CIN = 3, COUT = 64;

    extern __shared__ char smraw[];
    ull*   wpk = (ull*)smraw;
    float* sEf = (float*)(smraw + 38400);
    float* sOf = (float*)(smraw + 48000);

    const int tid = threadIdx.x;
    const int OW0 = blockIdx.x * 32;
    const int OH0 = blockIdx.y * 16;
    const int bz  = blockIdx.z;
    const int b   = bz >> 2;       // batch
    const int cog = bz & 3;        // co group of 16

    // ---- prepack weights: wpk[(r*16+co)*75 + tap] = (w[2r][CO][tap], w[2r+1][CO][tap]) ----
    for (int idx = tid; idx < 4800; idx += 256) {
        int tap  = idx % 75;
        int rest = idx / 75;       // = r*16 + co
        int co   = rest & 15;
        int r    = rest >> 4;
        int CO   = cog * 16 + co;
        float we = w[((2 * r) * COUT + CO) * 75 + tap];
        float wo = w[((2 * r + 1) * COUT + CO) * 75 + tap];
        float2 pk = make_float2(we, wo);
        wpk[idx] = *(ull*)&pk;
    }

    // ---- fill input tile: rows OH0-2 .. OH0+17, cols OW0-2 .. OW0+33, zero padded ----
    for (int idx = tid; idx < 3 * 20 * 36; idx += 256) {
        int cc   = idx % 36;
        int rest = idx / 36;
        int rr   = rest % 20;
        int ci   = rest / 20;
        int gh = OH0 - 2 + rr;
        int gc = OW0 - 2 + cc;
        float v = 0.0f;
        if ((unsigned)gh < (unsigned)H && (unsigned)gc < (unsigned)W)
            v = x[((b * CIN + ci) * H + gh) * W + gc];
        int base = (ci * 20 + rr) * 40;
        sEf[base + cc] = v;
        if (cc >= 1) sOf[base + cc - 1] = v;   // shifted copy
    }
    __syncthreads();

    // ---- per-thread compute: fixed co + output row, 32 cols ----
    const int co  = tid & 15;
    const int row = tid >> 4;           // 0..15
    const int oh  = OH0 + row;
    const int r   = row & 3;            // OH0 multiple of 16
    const int CO  = cog * 16 + co;

    float2 bp = make_float2(bias[(2 * r) * COUT + CO],
                            bias[(2 * r + 1) * COUT + CO]);
    const ull binit = *(ull*)&bp;

    ull acc[16];
#pragma unroll
    for (int j = 0; j < 16; j++) acc[j] = binit;

    const ull* wbase = wpk + (r * 16 + co) * 75;

#pragma unroll 1
    for (int ci = 0; ci < 3; ci++) {
#pragma unroll 1
        for (int kh = 0; kh < 5; kh++) {
            int srow = row + kh;                       // smem row = global - (OH0-2)
            const ull* eP = (const ull*)(sEf + (ci * 20 + srow) * 40);
            const ull* oP = (const ull*)(sOf + (ci * 20 + srow) * 40);
            const ull* wp = wbase + ci * 25 + kh * 5;
            ull w0 = wp[0], w1 = wp[1], w2 = wp[2], w3 = wp[3], w4 = wp[4];

            // acc j covers cols (OW0+2j, OW0+2j+1).
            // kw=0: eP[j], kw=1: oP[j], kw=2: eP[j+1], kw=3: oP[j+1], kw=4: eP[j+2]
#pragma unroll
            for (int j = 0; j < 8; j++) {
                fma2(acc[j], eP[j],     w0);
                fma2(acc[j], oP[j],     w1);
                fma2(acc[j], eP[j + 1], w2);
                fma2(acc[j], oP[j + 1], w3);
                fma2(acc[j], eP[j + 2], w4);
            }
#pragma unroll
            for (int j = 8; j < 16; j++) {
                fma2(acc[j], eP[j],     w0);
                fma2(acc[j], oP[j],     w1);
                fma2(acc[j], eP[j + 1], w2);
                fma2(acc[j], oP[j + 1], w3);
                fma2(acc[j], eP[j + 2], w4);
            }
        }
    }

    // ---- store: 32 consecutive floats, 128B-aligned -> 8x STG.128 ----
    float* op = out + (((size_t)(b * COUT + CO)) * H + oh) * W + OW0;
#pragma unroll
    for (int k = 0; k < 8; k++) {
        ulonglong2 v;
        v.x = acc[2 * k];
        v.y = acc[2 * k + 1];
        ((ulonglong2*)op)[k] = v;
    }
}

extern "C" void kernel_launch(void* const* d_in, const int* in_sizes, int n_in,
                              void* d_out, int out_size)
{
    // Map inputs by element count (robust to ordering):
    //   x: 2*3*720*1280 = 5529600, w: 8*64*3*5*5 = 38400, b: 8*64 = 512
    const float* x = nullptr;
    const float* w = nullptr;
    const float* bb = nullptr;
    for (int i = 0; i < n_in; i++) {
        if (in_sizes[i] == 5529600)     x  = (const float*)d_in[i];
        else if (in_sizes[i] == 38400)  w  = (const float*)d_in[i];
        else if (in_sizes[i] == 512)    bb = (const float*)d_in[i];
    }
    float* out = (float*)d_out;

    cudaFuncSetAttribute(svc8_kernel,
                         cudaFuncAttributeMaxDynamicSharedMemorySize, SMEM_BYTES);

    dim3 grid(1280 / 32, 720 / 16, 2 * 4);   // (col tiles, row tiles, batch*cogroup)
    svc8_kernel<<<grid, 256, SMEM_BYTES>>>(x, w, bb, out);
}

// round 2
// speedup vs baseline: 1.0524x; 1.0524x over previous
#include <cuda_runtime.h>
#include <cuda_bf16.h>

// SVC8 5x5: out[b,co,oh,ow] = bias[i,co] + sum_{ci,kh,kw} x[b,ci,oh+kh-2,ow+kw-2] * w[i,co,ci,kh,kw]
// where i = 2*(oh%4) + (ow%2), zero padding outside.
//
// f32x2 packed FMA (FFMA2). Thread: fixed (b, co, oh), 32 consecutive output
// columns as 16 f32x2 accumulators. Even/odd lane of an output pair uses conv
// 2r / 2r+1 -> weight operand is a prepacked (w_even, w_odd) pair. Input
// operand pairs: even-offset pairs come straight from LDS.128 (ulonglong2 =
// two aligned pairs per load); odd-offset pairs are built in registers
// (2 MOVs), eliminating the duplicated shifted smem copy of round 1.

typedef unsigned long long ull;

__device__ __forceinline__ void fma2(ull& d, ull a, ull b) {
    asm("fma.rn.f32x2 %0, %1, %2, %0;" : "+l"(d) : "l"(a), "l"(b));
}

// build pair (hi32(a), lo32(b))
__device__ __forceinline__ ull shf_pair(ull a, ull b) {
    ull r;
    asm("{ .reg .b32 x,y,z,w;\n\t"
        "mov.b64 {x,y}, %1;\n\t"
        "mov.b64 {z,w}, %2;\n\t"
        "mov.b64 %0, {y,z}; }"
        : "=l"(r) : "l"(a), "l"(b));
    return r;
}

// smem layout (dynamic, 55680 B):
//   [0,     38400)  ull   wpk[4][16][75]   packed (w_even, w_odd) pairs
//   [38400, 55680)  float sEf[3][20][72]   input tile, cols OW0-2 .. OW0+65 (68 used)
#define SMEM_BYTES 55680

__global__ void __launch_bounds__(512, 2) svc8_kernel(
    const float* __restrict__ x,
    const float* __restrict__ w,
    const float* __restrict__ bias,
    float* __restrict__ out)
{
    constexpr int H = 720, W = 1280, CIN = 3, COUT = 64;

    extern __shared__ char smraw[];
    ull*   wpk = (ull*)smraw;
    float* sEf = (float*)(smraw + 38400);

    const int tid = threadIdx.x;
    const int OW0 = blockIdx.x * 64;
    const int OH0 = blockIdx.y * 16;
    const int bz  = blockIdx.z;
    const int b   = bz >> 2;       // batch
    const int cog = bz & 3;        // co group of 16

    // ---- prepack weights: wpk[(r*16+co)*75 + tap] = (w[2r][CO][tap], w[2r+1][CO][tap]) ----
    for (int idx = tid; idx < 4800; idx += 512) {
        int tap  = idx % 75;
        int rest = idx / 75;       // r*16 + co
        int co   = rest & 15;
        int r    = rest >> 4;
        int CO   = cog * 16 + co;
        float we = w[((2 * r) * COUT + CO) * 75 + tap];
        float wo = w[((2 * r + 1) * COUT + CO) * 75 + tap];
        float2 pk = make_float2(we, wo);
        wpk[idx] = *(ull*)&pk;
    }

    // ---- fill input tile: rows OH0-2 .. OH0+17, cols OW0-2 .. OW0+65 ----
    for (int idx = tid; idx < 3 * 20 * 68; idx += 512) {
        int cc   = idx % 68;
        int rest = idx / 68;
        int rr   = rest % 20;
        int ci   = rest / 20;
        int gh = OH0 - 2 + rr;
        int gc = OW0 - 2 + cc;
        float v = 0.0f;
        if ((unsigned)gh < (unsigned)H && (unsigned)gc < (unsigned)W)
            v = x[((b * CIN + ci) * H + gh) * W + gc];
        sEf[(ci * 20 + rr) * 72 + cc] = v;
    }
    __syncthreads();

    // ---- per-thread compute: fixed co + output row + col-half, 32 cols ----
    const int co   = tid & 15;
    const int row  = (tid >> 4) & 15;    // 0..15
    const int half = tid >> 8;           // 0/1
    const int OWo  = half * 32;          // column offset within tile
    const int oh   = OH0 + row;
    const int r    = row & 3;            // OH0 multiple of 16
    const int CO   = cog * 16 + co;

    float2 bp = make_float2(bias[(2 * r) * COUT + CO],
                            bias[(2 * r + 1) * COUT + CO]);
    const ull binit = *(ull*)&bp;

    ull acc[16];
#pragma unroll
    for (int j = 0; j < 16; j++) acc[j] = binit;

    const ull* wbase = wpk + (r * 16 + co) * 75;

#pragma unroll 1
    for (int ci = 0; ci < 3; ci++) {
#pragma unroll 1
        for (int kh = 0; kh < 5; kh++) {
            int srow = row + kh;         // smem row index (global row - (OH0-2))
            const ulonglong2* eQ =
                (const ulonglong2*)(sEf + (ci * 20 + srow) * 72 + OWo);
            const ull* wp = wbase + ci * 25 + kh * 5;
            ull w0 = wp[0], w1 = wp[1], w2 = wp[2], w3 = wp[3], w4 = wp[4];

            // acc j covers output cols (OWb+2j, OWb+2j+1), OWb = OW0+OWo.
            // taps: kw0 -> e[j], kw1 -> o[j], kw2 -> e[j+1], kw3 -> o[j+1], kw4 -> e[j+2]
            // e[p] = aligned pair p; o[p] = (e[p].y, e[p+1].x) built in regs.
            ulonglong2 q = eQ[0];                 // e[0], e[1]
            ull oA = shf_pair(q.x, q.y);          // o[0]
#pragma unroll
            for (int m = 0; m < 8; m++) {
                ulonglong2 qn = eQ[m + 1];        // e[2m+2], e[2m+3]
                ull oB = shf_pair(q.y, qn.x);     // o[2m+1]
                ull oC = shf_pair(qn.x, qn.y);    // o[2m+2]

                fma2(acc[2 * m],     q.x,  w0);
                fma2(acc[2 * m],     oA,   w1);
                fma2(acc[2 * m],     q.y,  w2);
                fma2(acc[2 * m],     oB,   w3);
                fma2(acc[2 * m],     qn.x, w4);

                fma2(acc[2 * m + 1], q.y,  w0);
                fma2(acc[2 * m + 1], oB,   w1);
                fma2(acc[2 * m + 1], qn.x, w2);
                fma2(acc[2 * m + 1], oC,   w3);
                fma2(acc[2 * m + 1], qn.y, w4);

                q = qn;
                oA = oC;
            }
        }
    }

    // ---- store: 32 consecutive floats, 128B-aligned -> 8x STG.128 ----
    float* op = out + (((size_t)(b * COUT + CO)) * H + oh) * W + OW0 + OWo;
#pragma unroll
    for (int k = 0; k < 8; k++) {
        ulonglong2 v;
        v.x = acc[2 * k];
        v.y = acc[2 * k + 1];
        ((ulonglong2*)op)[k] = v;
    }
}

extern "C" void kernel_launch(void* const* d_in, const int* in_sizes, int n_in,
                              void* d_out, int out_size)
{
    // x: 2*3*720*1280 = 5529600, w: 8*64*3*5*5 = 38400, b: 8*64 = 512
    const float* x = nullptr;
    const float* w = nullptr;
    const float* bb = nullptr;
    for (int i = 0; i < n_in; i++) {
        if (in_sizes[i] == 5529600)     x  = (const float*)d_in[i];
        else if (in_sizes[i] == 38400)  w  = (const float*)d_in[i];
        else if (in_sizes[i] == 512)    bb = (const float*)d_in[i];
    }
    float* out = (float*)d_out;

    cudaFuncSetAttribute(svc8_kernel,
                         cudaFuncAttributeMaxDynamicSharedMemorySize, SMEM_BYTES);

    dim3 grid(1280 / 64, 720 / 16, 2 * 4);   // (col tiles, row tiles, batch*cogroup)
    svc8_kernel<<<grid, 512, SMEM_BYTES>>>(x, w, bb, out);
}

// round 3
// speedup vs baseline: 1.1552x; 1.0976x over previous
#include <cuda_runtime.h>
#include <cuda_bf16.h>

// SVC8 5x5: out[b,co,oh,ow] = bias[i,co] + sum_{ci,kh,kw} x[b,ci,oh+kh-2,ow+kw-2] * w[i,co,ci,kh,kw]
// where i = 2*(oh%4) + (ow%2), zero padding outside.
//
// f32x2 packed FMA (FFMA2). Thread: fixed (b, co, oh), 32 consecutive output
// columns as 16 f32x2 accumulators. Even/odd lane of an output pair uses conv
// 2r / 2r+1 -> weight operand is a prepacked (w_even, w_odd) pair. Even input
// pairs come from LDS.128; odd pairs are built in registers.
//
// R3: each CTA prepacks weights ONCE and sweeps 4 column-tiles (256 output
// cols), refilling only the input tile per pass. Grid 7200 -> 1800 CTAs,
// weight-prepack gmem/smem traffic /4. float2 input fill, running pointers.

typedef unsigned long long ull;

__device__ __forceinline__ void fma2(ull& d, ull a, ull b) {
    asm("fma.rn.f32x2 %0, %1, %2, %0;" : "+l"(d) : "l"(a), "l"(b));
}

// build pair (hi32(a), lo32(b))
__device__ __forceinline__ ull shf_pair(ull a, ull b) {
    ull r;
    asm("{ .reg .b32 x,y,z,w;\n\t"
        "mov.b64 {x,y}, %1;\n\t"
        "mov.b64 {z,w}, %2;\n\t"
        "mov.b64 %0, {y,z}; }"
        : "=l"(r) : "l"(a), "l"(b));
    return r;
}

// smem layout (dynamic, 55680 B):
//   [0,     38400)  ull   wpk[4][16][75]   packed (w_even, w_odd) pairs
//   [38400, 55680)  float sEf[3][20][72]   input tile, cols OW0-2 .. OW0+65 (68 used)
#define SMEM_BYTES 55680

__global__ void __launch_bounds__(512, 2) svc8_kernel(
    const float* __restrict__ x,
    const float* __restrict__ w,
    const float* __restrict__ bias,
    float* __restrict__ out)
{
    constexpr int H = 720, W = 1280, CIN = 3, COUT = 64;

    extern __shared__ char smraw[];
    ull*   wpk = (ull*)smraw;
    float* sEf = (float*)(smraw + 38400);

    const int tid = threadIdx.x;
    const int OWB = blockIdx.x * 256;    // CTA column base (4 passes of 64)
    const int OH0 = blockIdx.y * 16;
    const int bz  = blockIdx.z;
    const int b   = bz >> 2;             // batch
    const int cog = bz & 3;              // co group of 16

    // ---- prepack weights ONCE: wpk[(r*16+co)*75 + tap] = (w[2r][CO][tap], w[2r+1][CO][tap]) ----
    for (int idx = tid; idx < 4800; idx += 512) {
        int tap  = idx % 75;
        int rest = idx / 75;             // r*16 + co
        int co   = rest & 15;
        int r    = rest >> 4;
        int CO   = cog * 16 + co;
        float we = __ldg(&w[((2 * r) * COUT + CO) * 75 + tap]);
        float wo = __ldg(&w[((2 * r + 1) * COUT + CO) * 75 + tap]);
        float2 pk = make_float2(we, wo);
        wpk[idx] = *(ull*)&pk;
    }

    // ---- per-thread constants ----
    const int co   = tid & 15;
    const int row  = (tid >> 4) & 15;    // 0..15
    const int half = tid >> 8;           // 0/1
    const int OWo  = half * 32;          // column offset within 64-wide pass tile
    const int oh   = OH0 + row;
    const int r    = row & 3;            // OH0 multiple of 16
    const int CO   = cog * 16 + co;

    float2 bp = make_float2(bias[(2 * r) * COUT + CO],
                            bias[(2 * r + 1) * COUT + CO]);
    const ull binit = *(ull*)&bp;
    const ull* wbase = wpk + (r * 16 + co) * 75;

    // fill decomposition (float2): 3*20*34 = 2040 pairs over 512 threads
    const int f_cc2  = tid & 31;                 // *not* direct: decode below
    (void)f_cc2;

#pragma unroll 1
    for (int pass = 0; pass < 4; pass++) {
        const int OW0 = OWB + pass * 64;

        if (pass > 0) __syncthreads();   // previous pass reads done

        // ---- fill input tile: rows OH0-2..OH0+17, cols OW0-2..OW0+65, float2 ----
        for (int idx = tid; idx < 3 * 20 * 34; idx += 512) {
            int c2   = idx % 34;                 // float2 index within row
            int rest = idx / 34;
            int rr   = rest % 20;
            int ci   = rest / 20;
            int gh = OH0 - 2 + rr;
            int gc = OW0 - 2 + c2 * 2;           // even
            float2 v = make_float2(0.f, 0.f);
            if ((unsigned)gh < (unsigned)H) {
                const float* xr = x + ((b * CIN + ci) * H + gh) * W;
                if ((unsigned)gc < (unsigned)W && (unsigned)(gc + 1) < (unsigned)W) {
                    v = *(const float2*)(xr + gc);
                } else {
                    if ((unsigned)gc < (unsigned)W)     v.x = xr[gc];
                    if ((unsigned)(gc + 1) < (unsigned)W) v.y = xr[gc + 1];
                }
            }
            *(float2*)(sEf + (ci * 20 + rr) * 72 + c2 * 2) = v;
        }
        __syncthreads();

        // ---- compute: 16 f32x2 accs = 32 output cols ----
        ull acc[16];
#pragma unroll
        for (int j = 0; j < 16; j++) acc[j] = binit;

        const ull* wp = wbase;
        const float* srowp = sEf + row * 72 + OWo;

#pragma unroll 1
        for (int ci = 0; ci < 3; ci++) {
#pragma unroll 1
            for (int kh = 0; kh < 5; kh++) {
                const ulonglong2* eQ = (const ulonglong2*)srowp;
                ull w0 = wp[0], w1 = wp[1], w2 = wp[2], w3 = wp[3], w4 = wp[4];
                wp += 5;
                srowp += 72;

                // acc j covers cols (OWb+2j, OWb+2j+1).
                // taps: kw0->e[j], kw1->o[j], kw2->e[j+1], kw3->o[j+1], kw4->e[j+2]
                ulonglong2 q = eQ[0];
                ull oA = shf_pair(q.x, q.y);
#pragma unroll
                for (int m = 0; m < 8; m++) {
                    ulonglong2 qn = eQ[m + 1];
                    ull oB = shf_pair(q.y, qn.x);
                    ull oC = shf_pair(qn.x, qn.y);

                    fma2(acc[2 * m],     q.x,  w0);
                    fma2(acc[2 * m],     oA,   w1);
                    fma2(acc[2 * m],     q.y,  w2);
                    fma2(acc[2 * m],     oB,   w3);
                    fma2(acc[2 * m],     qn.x, w4);

                    fma2(acc[2 * m + 1], q.y,  w0);
                    fma2(acc[2 * m + 1], oB,   w1);
                    fma2(acc[2 * m + 1], qn.x, w2);
                    fma2(acc[2 * m + 1], oC,   w3);
                    fma2(acc[2 * m + 1], qn.y, w4);

                    q = qn;
                    oA = oC;
                }
            }
            srowp += (20 - 5) * 72;   // next ci plane
        }

        // ---- store: 32 consecutive floats -> 8x STG.128 ----
        float* op = out + (((size_t)(b * COUT + CO)) * H + oh) * W + OW0 + OWo;
#pragma unroll
        for (int k = 0; k < 8; k++) {
            ulonglong2 v;
            v.x = acc[2 * k];
            v.y = acc[2 * k + 1];
            ((ulonglong2*)op)[k] = v;
        }
    }
}

extern "C" void kernel_launch(void* const* d_in, const int* in_sizes, int n_in,
                              void* d_out, int out_size)
{
    // x: 2*3*720*1280 = 5529600, w: 8*64*3*5*5 = 38400, b: 8*64 = 512
    const float* x = nullptr;
    const float* w = nullptr;
    const float* bb = nullptr;
    for (int i = 0; i < n_in; i++) {
        if (in_sizes[i] == 5529600)     x  = (const float*)d_in[i];
        else if (in_sizes[i] == 38400)  w  = (const float*)d_in[i];
        else if (in_sizes[i] == 512)    bb = (const float*)d_in[i];
    }
    float* out = (float*)d_out;

    cudaFuncSetAttribute(svc8_kernel,
                         cudaFuncAttributeMaxDynamicSharedMemorySize, SMEM_BYTES);

    dim3 grid(1280 / 256, 720 / 16, 2 * 4);   // (4-pass col tiles, row tiles, batch*cogroup)
    svc8_kernel<<<grid, 512, SMEM_BYTES>>>(x, w, bb, out);
}

// round 5
// speedup vs baseline: 1.3217x; 1.1442x over previous
#include <cuda_runtime.h>
#include <cuda_bf16.h>
#include <cstdint>

// SVC8 5x5 via warp-level mma.sync bf16 implicit GEMM (3-term split, fp32 acc).
//
// For fixed phase-row r (oh = 4p + r) and phase-col c (ow = 2q + c):
//   out[(c,co)][q] = bias + sum_{t,ci,kh} W[(c,co)][(t,ci,kh)] * B[(t,ci,kh)][q]
// Taps t = (plane pi in {even,odd}) x (q-offset off in {-1,0,+1});
//   B[(t,ci,kh)][q] = x[ci][4p+r-2+kh][2(q+off)+pi]
//   W[(c,co)][(t,ci,kh)] = w[2r+c][co][ci][kh][kw], kw = 2*off+pi-c+2 (else 0)
// M = 128 (c*64+co), K = 6*16 = 96 (15 of 16 used per tap), N = 64 q.
//
// bf16 Markidis split: v = hi + lo; D = Ahi*Bhi + Ahi*Blo + Alo*Bhi.
// SMEM holds A and B in *fragment order*: each mma fragment is a contiguous
// 32-lane run (A: 16B/lane, B: 8B/lane) -> plain LDS.128/LDS.64, no conflicts.

typedef unsigned int u32;

#define A_HI 0
#define A_LO 24576
#define B_HI 49152
#define B_LO 61440
#define DS_OFF 49152            // epilogue bounce overlays B region
#define SMEM_BYTES 81920

__device__ __forceinline__ u32 pk_bf16(float lo, float hi) {
    u32 r;
    asm("cvt.rn.bf16x2.f32 %0, %1, %2;" : "=r"(r) : "f"(hi), "f"(lo));
    return r;
}
__device__ __forceinline__ float lo_f(u32 h) { return __uint_as_float(h << 16); }
__device__ __forceinline__ float hi_f(u32 h) { return __uint_as_float(h & 0xFFFF0000u); }

__device__ __forceinline__ void mma16816(float* d, const u32* a, const u32* b) {
    asm volatile(
        "mma.sync.aligned.m16n8k16.row.col.f32.bf16.bf16.f32 "
        "{%0,%1,%2,%3}, {%4,%5,%6,%7}, {%8,%9}, {%0,%1,%2,%3};"
        : "+f"(d[0]), "+f"(d[1]), "+f"(d[2]), "+f"(d[3])
        : "r"(a[0]), "r"(a[1]), "r"(a[2]), "r"(a[3]), "r"(b[0]), "r"(b[1]));
}

__global__ void __launch_bounds__(256, 2) svc8_mma_kernel(
    const float* __restrict__ x,
    const float* __restrict__ w,
    const float* __restrict__ bias,
    float* __restrict__ out)
{
    extern __shared__ __align__(16) char smraw[];
    float* Ds = (float*)(smraw + DS_OFF);

    const int tid  = threadIdx.x;
    const int wid  = tid >> 5;
    const int lane = tid & 31;
    const int g    = lane >> 2;     // fragment group row
    const int t    = lane & 3;      // fragment thread-in-group

    const int q0 = blockIdx.x * 64;
    const int p0 = blockIdx.y * 12;
    const int b  = blockIdx.z >> 2;
    const int r  = blockIdx.z & 3;

    // ---- A prepack (once): fragment order, 48 frags x 32 lanes, hi+lo ----
    // frag = kt*8 + mt;  a-regs: (row, k) = (g,2t),(g+8,2t),(g,2t+8),(g+8,2t+8) +pair
    for (int s = tid; s < 1536; s += 256) {
        int ln = s & 31, frag = s >> 5;
        int kt = frag >> 3, mt = frag & 7;
        int gg = ln >> 2, tt = ln & 3;
        int pi = kt & 1, off = (kt >> 1) - 1;
        u32 hv[4], lv[4];
#pragma unroll
        for (int rrg = 0; rrg < 4; rrg++) {
            int m   = mt * 16 + gg + ((rrg & 1) ? 8 : 0);
            int kbs = 2 * tt + ((rrg & 2) ? 8 : 0);
            int c = m >> 6, co = m & 63;
            int kw = 2 * off + pi - c + 2;
            float v0 = 0.f, v1 = 0.f;
            if (kw >= 0 && kw < 5) {
                const float* wb = w + ((size_t)((2 * r + c) * 64 + co)) * 75 + kw;
#pragma unroll
                for (int j = 0; j < 2; j++) {
                    int idx = kbs + j;
                    if (idx < 15) {
                        int ci = idx / 5, kh = idx - ci * 5;
                        float vv = wb[ci * 25 + kh * 5];
                        if (j == 0) v0 = vv; else v1 = vv;
                    }
                }
            }
            u32 h = pk_bf16(v0, v1);
            hv[rrg] = h;
            lv[rrg] = pk_bf16(v0 - lo_f(h), v1 - hi_f(h));
        }
        ((uint4*)(smraw + A_HI))[frag * 32 + ln] = make_uint4(hv[0], hv[1], hv[2], hv[3]);
        ((uint4*)(smraw + A_LO))[frag * 32 + ln] = make_uint4(lv[0], lv[1], lv[2], lv[3]);
    }

    // ---- warp tiling: warp = (mq, nq); tile M32 x N32 ----
    const int mq = wid & 3, nq = wid >> 2;
    const int mt0 = mq * 2;         // m16-frag base
    const int nt0 = nq * 4;         // n8-frag base

    // bias folded into accumulator init
    float bini[2][2];
#pragma unroll
    for (int mi = 0; mi < 2; mi++)
#pragma unroll
        for (int h = 0; h < 2; h++) {
            int m = mq * 32 + mi * 16 + g + 8 * h;
            bini[mi][h] = bias[(2 * r + (m >> 6)) * 64 + (m & 63)];
        }

    // ---- p loop ----
#pragma unroll 1
    for (int it = 0; it < 12; it++) {
        const int p = p0 + it;

        __syncthreads();   // prev iter Ds reads done -> B region free

        // ---- B fill: fragment order, 48 frags x 32 lanes, hi+lo ----
        for (int s = tid; s < 1536; s += 256) {
            int ln = s & 31, frag = s >> 5;
            int kt = frag >> 3, nt = frag & 7;
            int gg = ln >> 2, tt = ln & 3;
            int pi = kt & 1, off = (kt >> 1) - 1;
            int colg = 2 * (q0 + nt * 8 + gg + off) + pi;
            float v[4] = {0.f, 0.f, 0.f, 0.f};
            if ((unsigned)colg < 1280u) {
                const float* xc = x + ((size_t)b * 3) * 720 * 1280 + colg;
#pragma unroll
                for (int j = 0; j < 4; j++) {
                    int idx = 2 * tt + ((j & 2) ? 8 : 0) + (j & 1);
                    if (idx < 15) {
                        int ci = idx / 5, kh = idx - ci * 5;
                        int rowg = 4 * p + r - 2 + kh;
                        if ((unsigned)rowg < 720u)
                            v[j] = __ldg(xc + ((size_t)ci * 720 + rowg) * 1280);
                    }
                }
            }
            u32 h0 = pk_bf16(v[0], v[1]);
            u32 h1 = pk_bf16(v[2], v[3]);
            u32 l0 = pk_bf16(v[0] - lo_f(h0), v[1] - hi_f(h0));
            u32 l1 = pk_bf16(v[2] - lo_f(h1), v[3] - hi_f(h1));
            ((uint2*)(smraw + B_HI))[frag * 32 + ln] = make_uint2(h0, h1);
            ((uint2*)(smraw + B_LO))[frag * 32 + ln] = make_uint2(l0, l1);
        }
        __syncthreads();

        // ---- compute: 2m x 4n frags, K = 6x16, 3 split terms ----
        float d[2][4][4];
#pragma unroll
        for (int mi = 0; mi < 2; mi++)
#pragma unroll
            for (int nj = 0; nj < 4; nj++) {
                d[mi][nj][0] = bini[mi][0];
                d[mi][nj][1] = bini[mi][0];
                d[mi][nj][2] = bini[mi][1];
                d[mi][nj][3] = bini[mi][1];
            }

#pragma unroll
        for (int kt = 0; kt < 6; kt++) {
            u32 ah[2][4], al[2][4];
#pragma unroll
            for (int mi = 0; mi < 2; mi++) {
                int fr = kt * 8 + mt0 + mi;
                uint4 vh = ((const uint4*)(smraw + A_HI))[fr * 32 + lane];
                uint4 vl = ((const uint4*)(smraw + A_LO))[fr * 32 + lane];
                ah[mi][0] = vh.x; ah[mi][1] = vh.y; ah[mi][2] = vh.z; ah[mi][3] = vh.w;
                al[mi][0] = vl.x; al[mi][1] = vl.y; al[mi][2] = vl.z; al[mi][3] = vl.w;
            }
            u32 bh[4][2], bl[4][2];
#pragma unroll
            for (int nj = 0; nj < 4; nj++) {
                int fr = kt * 8 + nt0 + nj;
                uint2 vh = ((const uint2*)(smraw + B_HI))[fr * 32 + lane];
                uint2 vl = ((const uint2*)(smraw + B_LO))[fr * 32 + lane];
                bh[nj][0] = vh.x; bh[nj][1] = vh.y;
                bl[nj][0] = vl.x; bl[nj][1] = vl.y;
            }
#pragma unroll
            for (int mi = 0; mi < 2; mi++)
#pragma unroll
                for (int nj = 0; nj < 4; nj++) {
                    mma16816(d[mi][nj], ah[mi], bh[nj]);
                    mma16816(d[mi][nj], ah[mi], bl[nj]);
                    mma16816(d[mi][nj], al[mi], bh[nj]);
                }
        }

        __syncthreads();   // all warps done reading B -> Ds region free

        // ---- epilogue 1: c-frags -> swizzled bounce Ds[n*128 + (m ^ ((n&7)<<2))] ----
#pragma unroll
        for (int mi = 0; mi < 2; mi++)
#pragma unroll
            for (int nj = 0; nj < 4; nj++) {
                int m0 = mq * 32 + mi * 16 + g;
                int n0 = nq * 32 + nj * 8 + 2 * t;
                int x0 = (n0 & 7) << 2, x1 = ((n0 + 1) & 7) << 2;
                Ds[n0 * 128       + (m0 ^ x0)]       = d[mi][nj][0];
                Ds[(n0 + 1) * 128 + (m0 ^ x1)]       = d[mi][nj][1];
                Ds[n0 * 128       + ((m0 + 8) ^ x0)] = d[mi][nj][2];
                Ds[(n0 + 1) * 128 + ((m0 + 8) ^ x1)] = d[mi][nj][3];
            }
        __syncthreads();

        // ---- epilogue 2: transposed read, interleave phases, STG.128 ----
        {
            const int co = tid & 63;
            const int ch = tid >> 6;    // 0..3
            float* orow = out + (((size_t)(b * 64 + co)) * 720 + (4 * p + r)) * 1280
                        + 2 * q0 + ch * 32;
#pragma unroll
            for (int j = 0; j < 8; j++) {
                int n = ch * 16 + 2 * j;
                int x0 = (n & 7) << 2, x1 = ((n + 1) & 7) << 2;
                float4 v;
                v.x = Ds[n * 128       + (co ^ x0)];
                v.y = Ds[n * 128       + ((co + 64) ^ x0)];
                v.z = Ds[(n + 1) * 128 + (co ^ x1)];
                v.w = Ds[(n + 1) * 128 + ((co + 64) ^ x1)];
                ((float4*)orow)[j] = v;
            }
        }
    }
}

extern "C" void kernel_launch(void* const* d_in, const int* in_sizes, int n_in,
                              void* d_out, int out_size)
{
    // x: 2*3*720*1280 = 5529600, w: 8*64*3*5*5 = 38400, b: 8*64 = 512
    const float* x = nullptr;
    const float* w = nullptr;
    const float* bb = nullptr;
    for (int i = 0; i < n_in; i++) {
        if (in_sizes[i] == 5529600)     x  = (const float*)d_in[i];
        else if (in_sizes[i] == 38400)  w  = (const float*)d_in[i];
        else if (in_sizes[i] == 512)    bb = (const float*)d_in[i];
    }
    float* out = (float*)d_out;

    cudaFuncSetAttribute(svc8_mma_kernel,
                         cudaFuncAttributeMaxDynamicSharedMemorySize, SMEM_BYTES);

    // 10 q-blocks (64 q), 15 p-strips (12 p), 2 batch x 4 phase-rows
    dim3 grid(10, 15, 8);
    svc8_mma_kernel<<<grid, 256, SMEM_BYTES>>>(x, w, bb, out);
}

// round 6
// speedup vs baseline: 1.4055x; 1.0633x over previous
#include <cuda_runtime.h>
#include <cuda_fp16.h>
#include <cstdint>

// SVC8 5x5 via warp-level mma.sync fp16 implicit GEMM (2-term A split, fp32 acc).
//
// For fixed phase-row r (oh = 4p + r) and phase-col c (ow = 2q + c):
//   out[(c,co)][q] = bias + sum_{t,ci,kh} W[(c,co)][(t,ci,kh)] * B[(t,ci,kh)][q]
// Taps t = (plane pi in {even,odd}) x (q-offset off in {-1,0,+1});
//   B[(t,ci,kh)][q] = x[ci][4p+r-2+kh][2(q+off)+pi]
//   W[(c,co)][(t,ci,kh)] = w[2r+c][co][ci][kh][kw], kw = 2*off+pi-c+2 (else 0)
// M = 128 (c*64+co), K = 6*16 = 96 (15 of 16 used per tap), N = 64 q.
//
// Precision: A = Ahi + Alo (fp16 pair, exact to ~2^-21); B single fp16 (~2^-11).
// D = Ahi*B + Alo*B, fp32 accumulate -> expected l2 rel err ~3e-4.
// SMEM in fragment order: each mma fragment is a contiguous 32-lane run
// (A: 16B/lane LDS.128, B: 8B/lane LDS.64), conflict-free.
// B fill is software-pipelined: next iter's x values prefetched into registers
// during the current iter's MMA phase.

typedef unsigned int u32;

#define A_HI   0
#define A_LO   24576
#define B_OFF  49152
#define DS_OFF 61440
#define SMEM_BYTES 94208

__device__ __forceinline__ u32 pk2(float v0, float v1) {
    __half2 h = __floats2half2_rn(v0, v1);   // v0 -> low half (even k)
    return *(u32*)&h;
}

__device__ __forceinline__ void mma16816(float* d, const u32* a, const u32* b) {
    asm volatile(
        "mma.sync.aligned.m16n8k16.row.col.f32.f16.f16.f32 "
        "{%0,%1,%2,%3}, {%4,%5,%6,%7}, {%8,%9}, {%0,%1,%2,%3};"
        : "+f"(d[0]), "+f"(d[1]), "+f"(d[2]), "+f"(d[3])
        : "r"(a[0]), "r"(a[1]), "r"(a[2]), "r"(a[3]), "r"(b[0]), "r"(b[1]));
}

__global__ void __launch_bounds__(256, 2) svc8_mma_kernel(
    const float* __restrict__ x,
    const float* __restrict__ w,
    const float* __restrict__ bias,
    float* __restrict__ out)
{
    extern __shared__ __align__(16) char smraw[];
    float* Ds = (float*)(smraw + DS_OFF);

    const int tid  = threadIdx.x;
    const int wid  = tid >> 5;
    const int lane = tid & 31;
    const int g    = lane >> 2;
    const int t    = lane & 3;

    const int q0 = blockIdx.x * 64;
    const int p0 = blockIdx.y * 12;
    const int b  = blockIdx.z >> 2;
    const int r  = blockIdx.z & 3;

    // ---- A prepack (once): fragment order, 48 frags x 32 lanes, fp16 hi+lo ----
    for (int s = tid; s < 1536; s += 256) {
        int ln = s & 31, frag = s >> 5;
        int kt = frag >> 3, mt = frag & 7;
        int gg = ln >> 2, tt = ln & 3;
        int pi = kt & 1, off = (kt >> 1) - 1;
        u32 hv[4], lv[4];
#pragma unroll
        for (int rrg = 0; rrg < 4; rrg++) {
            int m   = mt * 16 + gg + ((rrg & 1) ? 8 : 0);
            int kbs = 2 * tt + ((rrg & 2) ? 8 : 0);
            int c = m >> 6, co = m & 63;
            int kw = 2 * off + pi - c + 2;
            float v0 = 0.f, v1 = 0.f;
            if (kw >= 0 && kw < 5) {
                const float* wb = w + ((size_t)((2 * r + c) * 64 + co)) * 75 + kw;
#pragma unroll
                for (int j = 0; j < 2; j++) {
                    int idx = kbs + j;
                    if (idx < 15) {
                        int ci = idx / 5, kh = idx - ci * 5;
                        float vv = wb[ci * 25 + kh * 5];
                        if (j == 0) v0 = vv; else v1 = vv;
                    }
                }
            }
            __half h0 = __float2half_rn(v0), h1 = __float2half_rn(v1);
            hv[rrg] = pk2(v0, v1);                       // same rounding as h0,h1
            lv[rrg] = pk2(v0 - __half2float(h0), v1 - __half2float(h1));
        }
        ((uint4*)(smraw + A_HI))[frag * 32 + ln] = make_uint4(hv[0], hv[1], hv[2], hv[3]);
        ((uint4*)(smraw + A_LO))[frag * 32 + ln] = make_uint4(lv[0], lv[1], lv[2], lv[3]);
    }

    // ---- B-fill slot constants (6 slots/thread, fixed across iters) ----
    const float* sptr[6];
    int  stt[6];
    bool sok[6];
    u32  sst[6];
    const float* xb = x + (size_t)b * 3 * 720 * 1280;
#pragma unroll
    for (int s = 0; s < 6; s++) {
        int sid = s * 256 + tid;
        int ln = sid & 31, frag = sid >> 5;
        int kt = frag >> 3, nt = frag & 7;
        int gg = ln >> 2;
        stt[s] = ln & 3;
        int pi = kt & 1, off = (kt >> 1) - 1;
        int colg = 2 * (q0 + nt * 8 + gg + off) + pi;
        sok[s]  = (unsigned)colg < 1280u;
        sptr[s] = xb + (sok[s] ? colg : 0);
        sst[s]  = B_OFF + (u32)(frag * 32 + ln) * 8u;
    }

    // prefetch registers
    float pv[6][4];
    auto prefetch = [&](int p) {
#pragma unroll
        for (int s = 0; s < 6; s++)
#pragma unroll
            for (int j = 0; j < 4; j++) {
                int idx = 2 * stt[s] + ((j & 2) ? 8 : 0) + (j & 1);
                float v = 0.f;
                if (sok[s] && idx < 15) {
                    int ci = idx / 5, kh = idx - ci * 5;
                    int rowg = 4 * p + r - 2 + kh;
                    if ((unsigned)rowg < 720u)
                        v = __ldg(sptr[s] + ((size_t)ci * 720 + rowg) * 1280);
                }
                pv[s][j] = v;
            }
    };

    // ---- warp tiling: warp = (mq, nq); tile M32 x N32 ----
    const int mq = wid & 3, nq = wid >> 2;
    const int mt0 = mq * 2;
    const int nt0 = nq * 4;

    float bini[2][2];
#pragma unroll
    for (int mi = 0; mi < 2; mi++)
#pragma unroll
        for (int h = 0; h < 2; h++) {
            int m = mq * 32 + mi * 16 + g + 8 * h;
            bini[mi][h] = bias[(2 * r + (m >> 6)) * 64 + (m & 63)];
        }

    prefetch(p0);

    // ---- p loop ----
#pragma unroll 1
    for (int it = 0; it < 12; it++) {
        const int p = p0 + it;

        __syncthreads();   // prev iter's B reads + Ds reads complete

        // ---- store B (from prefetched regs), single fp16 ----
#pragma unroll
        for (int s = 0; s < 6; s++) {
            u32 h0 = pk2(pv[s][0], pv[s][1]);
            u32 h1 = pk2(pv[s][2], pv[s][3]);
            *(uint2*)(smraw + sst[s]) = make_uint2(h0, h1);
        }
        __syncthreads();

        // ---- prefetch next iter's x while MMAs run ----
        if (it < 11) prefetch(p + 1);

        // ---- compute: 2m x 4n frags, K = 6x16, 2 split terms ----
        float d[2][4][4];
#pragma unroll
        for (int mi = 0; mi < 2; mi++)
#pragma unroll
            for (int nj = 0; nj < 4; nj++) {
                d[mi][nj][0] = bini[mi][0];
                d[mi][nj][1] = bini[mi][0];
                d[mi][nj][2] = bini[mi][1];
                d[mi][nj][3] = bini[mi][1];
            }

#pragma unroll
        for (int kt = 0; kt < 6; kt++) {
            u32 ah[2][4], al[2][4];
#pragma unroll
            for (int mi = 0; mi < 2; mi++) {
                int fr = kt * 8 + mt0 + mi;
                uint4 vh = ((const uint4*)(smraw + A_HI))[fr * 32 + lane];
                uint4 vl = ((const uint4*)(smraw + A_LO))[fr * 32 + lane];
                ah[mi][0] = vh.x; ah[mi][1] = vh.y; ah[mi][2] = vh.z; ah[mi][3] = vh.w;
                al[mi][0] = vl.x; al[mi][1] = vl.y; al[mi][2] = vl.z; al[mi][3] = vl.w;
            }
            u32 bh[4][2];
#pragma unroll
            for (int nj = 0; nj < 4; nj++) {
                int fr = kt * 8 + nt0 + nj;
                uint2 vh = ((const uint2*)(smraw + B_OFF))[fr * 32 + lane];
                bh[nj][0] = vh.x; bh[nj][1] = vh.y;
            }
#pragma unroll
            for (int mi = 0; mi < 2; mi++)
#pragma unroll
                for (int nj = 0; nj < 4; nj++) {
                    mma16816(d[mi][nj], ah[mi], bh[nj]);
                    mma16816(d[mi][nj], al[mi], bh[nj]);
                }
        }

        // ---- epilogue 1: c-frags -> swizzled bounce Ds[n*128 + (m ^ ((n&7)<<2))] ----
#pragma unroll
        for (int mi = 0; mi < 2; mi++)
#pragma unroll
            for (int nj = 0; nj < 4; nj++) {
                int m0 = mq * 32 + mi * 16 + g;
                int n0 = nq * 32 + nj * 8 + 2 * t;
                int x0 = (n0 & 7) << 2, x1 = ((n0 + 1) & 7) << 2;
                Ds[n0 * 128       + (m0 ^ x0)]       = d[mi][nj][0];
                Ds[(n0 + 1) * 128 + (m0 ^ x1)]       = d[mi][nj][1];
                Ds[n0 * 128       + ((m0 + 8) ^ x0)] = d[mi][nj][2];
                Ds[(n0 + 1) * 128 + ((m0 + 8) ^ x1)] = d[mi][nj][3];
            }
        __syncthreads();

        // ---- epilogue 2: transposed read, interleave phases, STG.128 ----
        {
            const int co = tid & 63;
            const int ch = tid >> 6;
            float* orow = out + (((size_t)(b * 64 + co)) * 720 + (4 * p + r)) * 1280
                        + 2 * q0 + ch * 32;
#pragma unroll
            for (int j = 0; j < 8; j++) {
                int n = ch * 16 + 2 * j;
                int x0 = (n & 7) << 2, x1 = ((n + 1) & 7) << 2;
                float4 v;
                v.x = Ds[n * 128       + (co ^ x0)];
                v.y = Ds[n * 128       + ((co + 64) ^ x0)];
                v.z = Ds[(n + 1) * 128 + (co ^ x1)];
                v.w = Ds[(n + 1) * 128 + ((co + 64) ^ x1)];
                ((float4*)orow)[j] = v;
            }
        }
    }
}

extern "C" void kernel_launch(void* const* d_in, const int* in_sizes, int n_in,
                              void* d_out, int out_size)
{
    // x: 2*3*720*1280 = 5529600, w: 8*64*3*5*5 = 38400, b: 8*64 = 512
    const float* x = nullptr;
    const float* w = nullptr;
    const float* bb = nullptr;
    for (int i = 0; i < n_in; i++) {
        if (in_sizes[i] == 5529600)     x  = (const float*)d_in[i];
        else if (in_sizes[i] == 38400)  w  = (const float*)d_in[i];
        else if (in_sizes[i] == 512)    bb = (const float*)d_in[i];
    }
    float* out = (float*)d_out;

    cudaFuncSetAttribute(svc8_mma_kernel,
                         cudaFuncAttributeMaxDynamicSharedMemorySize, SMEM_BYTES);

    dim3 grid(10, 15, 8);
    svc8_mma_kernel<<<grid, 256, SMEM_BYTES>>>(x, w, bb, out);
}

// round 7
// speedup vs baseline: 1.4567x; 1.0365x over previous
#include <cuda_runtime.h>
#include <cuda_fp16.h>
#include <cstdint>

// SVC8 5x5 via warp-level mma.sync fp16 implicit GEMM (2-term A split, fp32 acc).
//
// For fixed phase-row r (oh = 4p + r) and phase-col c (ow = 2q + c):
//   out[(c,co)][q] = bias + sum_{t,ci,kh} W[(c,co)][(t,ci,kh)] * B[(t,ci,kh)][q]
// Taps t = (plane pi in {even,odd}) x (q-offset off in {-1,0,+1});
//   B[(t,ci,kh)][q] = x[ci][4p+r-2+kh][2(q+off)+pi]
// M = 128 (c*64+co), K = 6*16 = 96 (15 used per tap), N = 64 q.
//
// R7: x rows staged into smem via 4B cp.async (double-buffered, issued one
// iteration ahead -> gmem latency overlaps MMA). B tile built from the smem
// staging buffer (LDS, 29cyc) instead of scattered LDG (260cyc). No prefetch
// registers -> no spills (R6 was pinned at the 128-reg cap and spilling).

typedef unsigned int u32;

#define A_HI    0
#define A_LO    24576
#define B_OFF   49152
#define RAW_OFF 61440            // 2 x 15 rows x 132 floats = 2 x 7920 B
#define DS_OFF  77280
#define SMEM_BYTES 110048

__device__ __forceinline__ u32 smem_u32(const void* p) {
    u32 a;
    asm("{ .reg .u64 t; cvta.to.shared.u64 t, %1; cvt.u32.u64 %0, t; }"
        : "=r"(a) : "l"(p));
    return a;
}

__device__ __forceinline__ u32 pk2(float v0, float v1) {
    __half2 h = __floats2half2_rn(v0, v1);   // v0 -> low half (even k)
    return *(u32*)&h;
}

__device__ __forceinline__ void mma16816(float* d, const u32* a, const u32* b) {
    asm volatile(
        "mma.sync.aligned.m16n8k16.row.col.f32.f16.f16.f32 "
        "{%0,%1,%2,%3}, {%4,%5,%6,%7}, {%8,%9}, {%0,%1,%2,%3};"
        : "+f"(d[0]), "+f"(d[1]), "+f"(d[2]), "+f"(d[3])
        : "r"(a[0]), "r"(a[1]), "r"(a[2]), "r"(a[3]), "r"(b[0]), "r"(b[1]));
}

__global__ void __launch_bounds__(256, 2) svc8_mma_kernel(
    const float* __restrict__ x,
    const float* __restrict__ w,
    const float* __restrict__ bias,
    float* __restrict__ out)
{
    extern __shared__ __align__(16) char smraw[];
    float* Ds = (float*)(smraw + DS_OFF);

    const int tid  = threadIdx.x;
    const int wid  = tid >> 5;
    const int lane = tid & 31;
    const int g    = lane >> 2;
    const int t    = lane & 3;

    const int q0 = blockIdx.x * 64;
    const int p0 = blockIdx.y * 12;
    const int b  = blockIdx.z >> 2;
    const int r  = blockIdx.z & 3;

    const u32 smb = smem_u32(smraw);
    const float* xb = x + (size_t)b * 3 * 720 * 1280;
    const int gc0 = 2 * q0 - 2;

    // ---- cp.async staging of 15 row segments (132 floats each) ----
    auto stage = [&](int p, int buf) {
        const u32 dst0 = smb + RAW_OFF + (u32)buf * 7920u;
#pragma unroll 2
        for (int k = tid; k < 1980; k += 256) {
            int idx = k / 132;
            int cc  = k - idx * 132;
            int ci  = idx / 5;
            int kh  = idx - ci * 5;
            int grow = 4 * p + r - 2 + kh;
            int gcol = gc0 + cc;
            bool ok = ((unsigned)grow < 720u) && ((unsigned)gcol < 1280u);
            const float* src = ok ? (xb + ((size_t)ci * 720 + grow) * 1280 + gcol) : xb;
            u32 sz = ok ? 4u : 0u;
            asm volatile("cp.async.ca.shared.global [%0], [%1], 4, %2;"
                         :: "r"(dst0 + (u32)k * 4u), "l"(src), "r"(sz) : "memory");
        }
        asm volatile("cp.async.commit_group;" ::: "memory");
    };

    // ---- A prepack (once): fragment order, 48 frags x 32 lanes, fp16 hi+lo ----
    for (int s = tid; s < 1536; s += 256) {
        int ln = s & 31, frag = s >> 5;
        int kt = frag >> 3, mt = frag & 7;
        int gg = ln >> 2, tt = ln & 3;
        int pi = kt & 1, off = (kt >> 1) - 1;
        u32 hv[4], lv[4];
#pragma unroll
        for (int rrg = 0; rrg < 4; rrg++) {
            int m   = mt * 16 + gg + ((rrg & 1) ? 8 : 0);
            int kbs = 2 * tt + ((rrg & 2) ? 8 : 0);
            int c = m >> 6, co = m & 63;
            int kw = 2 * off + pi - c + 2;
            float v0 = 0.f, v1 = 0.f;
            if (kw >= 0 && kw < 5) {
                const float* wb = w + ((size_t)((2 * r + c) * 64 + co)) * 75 + kw;
#pragma unroll
                for (int j = 0; j < 2; j++) {
                    int idx = kbs + j;
                    if (idx < 15) {
                        int ci = idx / 5, kh = idx - ci * 5;
                        float vv = wb[ci * 25 + kh * 5];
                        if (j == 0) v0 = vv; else v1 = vv;
                    }
                }
            }
            __half h0 = __float2half_rn(v0), h1 = __float2half_rn(v1);
            hv[rrg] = pk2(v0, v1);
            lv[rrg] = pk2(v0 - __half2float(h0), v1 - __half2float(h1));
        }
        ((uint4*)(smraw + A_HI))[frag * 32 + ln] = make_uint4(hv[0], hv[1], hv[2], hv[3]);
        ((uint4*)(smraw + A_LO))[frag * 32 + ln] = make_uint4(lv[0], lv[1], lv[2], lv[3]);
    }

    stage(p0, 0);   // prefill buffer 0

    // ---- warp tiling: warp = (mq, nq); tile M32 x N32 ----
    const int mq = wid & 3, nq = wid >> 2;
    const int mt0 = mq * 2;
    const int nt0 = nq * 4;

    float bini[2][2];
#pragma unroll
    for (int mi = 0; mi < 2; mi++)
#pragma unroll
        for (int h = 0; h < 2; h++) {
            int m = mq * 32 + mi * 16 + g + 8 * h;
            bini[mi][h] = bias[(2 * r + (m >> 6)) * 64 + (m & 63)];
        }

    // ---- p loop ----
#pragma unroll 1
    for (int it = 0; it < 12; it++) {
        const int p   = p0 + it;
        const int buf = it & 1;

        asm volatile("cp.async.wait_group 0;" ::: "memory");
        __syncthreads();   // raw[buf] visible; prev iter's B/Ds reads done

        // ---- B fill from staged rows: kt = s, nt = wid (exact lane identity) ----
        {
            const float* rawb = (const float*)(smraw + RAW_OFF + buf * 7920);
            const int base_cc = 2 * (wid * 8 + g) + 2;
            const int tt = t;
#pragma unroll
            for (int s = 0; s < 6; s++) {
                int pi = s & 1, off = (s >> 1) - 1;
                const float* rp = rawb + base_cc + 2 * off + pi;
                float v0 = rp[(2 * tt) * 132];
                float v1 = rp[(2 * tt + 1) * 132];
                float v2 = rp[(2 * tt + 8) * 132];
                float v3 = (tt < 3) ? rp[(2 * tt + 9) * 132] : 0.f;
                u32 h0 = pk2(v0, v1);
                u32 h1 = pk2(v2, v3);
                *(uint2*)(smraw + B_OFF + (u32)(((s * 8 + wid) * 32 + lane) * 8)) =
                    make_uint2(h0, h1);
            }
        }

        if (it < 11) stage(p + 1, buf ^ 1);   // async, overlaps MMA below
        __syncthreads();

        // ---- compute: 2m x 4n frags, K = 6x16, 2 split terms ----
        float d[2][4][4];
#pragma unroll
        for (int mi = 0; mi < 2; mi++)
#pragma unroll
            for (int nj = 0; nj < 4; nj++) {
                d[mi][nj][0] = bini[mi][0];
                d[mi][nj][1] = bini[mi][0];
                d[mi][nj][2] = bini[mi][1];
                d[mi][nj][3] = bini[mi][1];
            }

#pragma unroll
        for (int kt = 0; kt < 6; kt++) {
            u32 ah[2][4], al[2][4];
#pragma unroll
            for (int mi = 0; mi < 2; mi++) {
                int fr = kt * 8 + mt0 + mi;
                uint4 vh = ((const uint4*)(smraw + A_HI))[fr * 32 + lane];
                uint4 vl = ((const uint4*)(smraw + A_LO))[fr * 32 + lane];
                ah[mi][0] = vh.x; ah[mi][1] = vh.y; ah[mi][2] = vh.z; ah[mi][3] = vh.w;
                al[mi][0] = vl.x; al[mi][1] = vl.y; al[mi][2] = vl.z; al[mi][3] = vl.w;
            }
            u32 bh[4][2];
#pragma unroll
            for (int nj = 0; nj < 4; nj++) {
                int fr = kt * 8 + nt0 + nj;
                uint2 vh = ((const uint2*)(smraw + B_OFF))[fr * 32 + lane];
                bh[nj][0] = vh.x; bh[nj][1] = vh.y;
            }
#pragma unroll
            for (int mi = 0; mi < 2; mi++)
#pragma unroll
                for (int nj = 0; nj < 4; nj++) {
                    mma16816(d[mi][nj], ah[mi], bh[nj]);
                    mma16816(d[mi][nj], al[mi], bh[nj]);
                }
        }

        // ---- epilogue 1: c-frags -> swizzled bounce Ds[n*128 + (m ^ ((n&7)<<2))] ----
#pragma unroll
        for (int mi = 0; mi < 2; mi++)
#pragma unroll
            for (int nj = 0; nj < 4; nj++) {
                int m0 = mq * 32 + mi * 16 + g;
                int n0 = nq * 32 + nj * 8 + 2 * t;
                int x0 = (n0 & 7) << 2, x1 = ((n0 + 1) & 7) << 2;
                Ds[n0 * 128       + (m0 ^ x0)]       = d[mi][nj][0];
                Ds[(n0 + 1) * 128 + (m0 ^ x1)]       = d[mi][nj][1];
                Ds[n0 * 128       + ((m0 + 8) ^ x0)] = d[mi][nj][2];
                Ds[(n0 + 1) * 128 + ((m0 + 8) ^ x1)] = d[mi][nj][3];
            }
        __syncthreads();

        // ---- epilogue 2: transposed read, interleave phases, STG.128 ----
        {
            const int co = tid & 63;
            const int ch = tid >> 6;
            float* orow = out + (((size_t)(b * 64 + co)) * 720 + (4 * p + r)) * 1280
                        + 2 * q0 + ch * 32;
#pragma unroll
            for (int j = 0; j < 8; j++) {
                int n = ch * 16 + 2 * j;
                int x0 = (n & 7) << 2, x1 = ((n + 1) & 7) << 2;
                float4 v;
                v.x = Ds[n * 128       + (co ^ x0)];
                v.y = Ds[n * 128       + ((co + 64) ^ x0)];
                v.z = Ds[(n + 1) * 128 + (co ^ x1)];
                v.w = Ds[(n + 1) * 128 + ((co + 64) ^ x1)];
                ((float4*)orow)[j] = v;
            }
        }
    }
}

extern "C" void kernel_launch(void* const* d_in, const int* in_sizes, int n_in,
                              void* d_out, int out_size)
{
    // x: 2*3*720*1280 = 5529600, w: 8*64*3*5*5 = 38400, b: 8*64 = 512
    const float* x = nullptr;
    const float* w = nullptr;
    const float* bb = nullptr;
    for (int i = 0; i < n_in; i++) {
        if (in_sizes[i] == 5529600)     x  = (const float*)d_in[i];
        else if (in_sizes[i] == 38400)  w  = (const float*)d_in[i];
        else if (in_sizes[i] == 512)    bb = (const float*)d_in[i];
    }
    float* out = (float*)d_out;

    cudaFuncSetAttribute(svc8_mma_kernel,
                         cudaFuncAttributeMaxDynamicSharedMemorySize, SMEM_BYTES);

    dim3 grid(10, 15, 8);
    svc8_mma_kernel<<<grid, 256, SMEM_BYTES>>>(x, w, bb, out);
}

// round 8
// speedup vs baseline: 1.5778x; 1.0831x over previous
#include <cuda_runtime.h>
#include <cuda_fp16.h>
#include <cstdint>

// SVC8 5x5 via warp-level mma.sync fp16 implicit GEMM (single fp16, fp32 acc).
//
// For fixed phase-row r (oh = 4p + r) and phase-col c (ow = 2q + c):
//   out[(c,co)][q] = bias + sum_{t,ci,kh} W[(c,co)][(t,ci,kh)] * B[(t,ci,kh)][q]
// Taps t = (plane pi in {even,odd}) x (q-offset off in {-1,0,+1});
//   B[(t,ci,kh)][q] = x[ci][4p+r-2+kh][2(q+off)+pi]
// M = 128 (c*64+co), K = 6*16 = 96 (15 used per tap), N = 64 q.
//
// R8: single-fp16 A (err ~3e-4 < 1e-3 gate) -> half the MMAs and A-LDS of R7;
// smem cut to 68KB (two-chunk epilogue) -> 3 CTAs/SM = 24 warps (was 16);
// B fragments stored pairwise -> LDS.128. cp.async staging double-buffered.

typedef unsigned int u32;

#define A_OFF   0
#define B_OFF   24576
#define RAW_OFF 36864            // 2 x 15 rows x 132 floats = 2 x 7920 B
#define DS_OFF  52704            // 32 x 128 floats = 16384 B (half-tile bounce)
#define SMEM_BYTES 69088

__device__ __forceinline__ u32 smem_u32(const void* p) {
    u32 a;
    asm("{ .reg .u64 t; cvta.to.shared.u64 t, %1; cvt.u32.u64 %0, t; }"
        : "=r"(a) : "l"(p));
    return a;
}

__device__ __forceinline__ u32 pk2(float v0, float v1) {
    __half2 h = __floats2half2_rn(v0, v1);   // v0 -> low half (even k)
    return *(u32*)&h;
}

__device__ __forceinline__ void mma16816(float* d, const u32* a, const u32* b) {
    asm volatile(
        "mma.sync.aligned.m16n8k16.row.col.f32.f16.f16.f32 "
        "{%0,%1,%2,%3}, {%4,%5,%6,%7}, {%8,%9}, {%0,%1,%2,%3};"
        : "+f"(d[0]), "+f"(d[1]), "+f"(d[2]), "+f"(d[3])
        : "r"(a[0]), "r"(a[1]), "r"(a[2]), "r"(a[3]), "r"(b[0]), "r"(b[1]));
}

__global__ void __launch_bounds__(256, 3) svc8_mma_kernel(
    const float* __restrict__ x,
    const float* __restrict__ w,
    const float* __restrict__ bias,
    float* __restrict__ out)
{
    extern __shared__ __align__(16) char smraw[];
    float* Ds = (float*)(smraw + DS_OFF);

    const int tid  = threadIdx.x;
    const int wid  = tid >> 5;
    const int lane = tid & 31;
    const int g    = lane >> 2;
    const int t    = lane & 3;

    const int q0 = blockIdx.x * 64;
    const int p0 = blockIdx.y * 12;
    const int b  = blockIdx.z >> 2;
    const int r  = blockIdx.z & 3;

    const u32 smb = smem_u32(smraw);
    const float* xb = x + (size_t)b * 3 * 720 * 1280;
    const int gc0 = 2 * q0 - 2;

    // ---- cp.async staging of 15 row segments (132 floats each) ----
    auto stage = [&](int p, int buf) {
        const u32 dst0 = smb + RAW_OFF + (u32)buf * 7920u;
#pragma unroll 2
        for (int k = tid; k < 1980; k += 256) {
            int idx = k / 132;
            int cc  = k - idx * 132;
            int ci  = idx / 5;
            int kh  = idx - ci * 5;
            int grow = 4 * p + r - 2 + kh;
            int gcol = gc0 + cc;
            bool ok = ((unsigned)grow < 720u) && ((unsigned)gcol < 1280u);
            const float* src = ok ? (xb + ((size_t)ci * 720 + grow) * 1280 + gcol) : xb;
            u32 sz = ok ? 4u : 0u;
            asm volatile("cp.async.ca.shared.global [%0], [%1], 4, %2;"
                         :: "r"(dst0 + (u32)k * 4u), "l"(src), "r"(sz) : "memory");
        }
        asm volatile("cp.async.commit_group;" ::: "memory");
    };

    // ---- A prepack (once): fragment order, 48 frags x 32 lanes, single fp16 ----
    for (int s = tid; s < 1536; s += 256) {
        int ln = s & 31, frag = s >> 5;
        int kt = frag >> 3, mt = frag & 7;
        int gg = ln >> 2, tt = ln & 3;
        int pi = kt & 1, off = (kt >> 1) - 1;
        u32 hv[4];
#pragma unroll
        for (int rrg = 0; rrg < 4; rrg++) {
            int m   = mt * 16 + gg + ((rrg & 1) ? 8 : 0);
            int kbs = 2 * tt + ((rrg & 2) ? 8 : 0);
            int c = m >> 6, co = m & 63;
            int kw = 2 * off + pi - c + 2;
            float v0 = 0.f, v1 = 0.f;
            if (kw >= 0 && kw < 5) {
                const float* wb = w + ((size_t)((2 * r + c) * 64 + co)) * 75 + kw;
#pragma unroll
                for (int j = 0; j < 2; j++) {
                    int idx = kbs + j;
                    if (idx < 15) {
                        int ci = idx / 5, kh = idx - ci * 5;
                        float vv = wb[ci * 25 + kh * 5];
                        if (j == 0) v0 = vv; else v1 = vv;
                    }
                }
            }
            hv[rrg] = pk2(v0, v1);
        }
        ((uint4*)(smraw + A_OFF))[frag * 32 + ln] = make_uint4(hv[0], hv[1], hv[2], hv[3]);
    }

    stage(p0, 0);   // prefill buffer 0

    // ---- warp tiling: warp = (mq, nq); tile M32 x N32 ----
    const int mq = wid & 3, nq = wid >> 2;
    const int mt0 = mq * 2;

    float bini[2][2];
#pragma unroll
    for (int mi = 0; mi < 2; mi++)
#pragma unroll
        for (int h = 0; h < 2; h++) {
            int m = mq * 32 + mi * 16 + g + 8 * h;
            bini[mi][h] = bias[(2 * r + (m >> 6)) * 64 + (m & 63)];
        }

    // ---- p loop ----
#pragma unroll 1
    for (int it = 0; it < 12; it++) {
        const int p   = p0 + it;
        const int buf = it & 1;

        asm volatile("cp.async.wait_group 0;" ::: "memory");
        __syncthreads();   // raw[buf] ready; prev iter's Ds reads done

        // ---- B fill from staged rows: kt = s, nt = wid; pairwise layout ----
        {
            const float* rawb = (const float*)(smraw + RAW_OFF + buf * 7920);
            const int base_cc = 2 * (wid * 8 + g) + 2;
            const u32 bdst = smb + B_OFF
                           + (u32)((wid >> 1) * 32 + lane) * 16u + (u32)(wid & 1) * 8u;
#pragma unroll
            for (int s = 0; s < 6; s++) {
                int pi = s & 1, off = (s >> 1) - 1;
                const float* rp = rawb + base_cc + 2 * off + pi;
                float v0 = rp[(2 * t) * 132];
                float v1 = rp[(2 * t + 1) * 132];
                float v2 = rp[(2 * t + 8) * 132];
                float v3 = (t < 3) ? rp[(2 * t + 9) * 132] : 0.f;
                u32 h0 = pk2(v0, v1);
                u32 h1 = pk2(v2, v3);
                asm volatile("st.shared.v2.b32 [%0], {%1, %2};"
                             :: "r"(bdst + (u32)s * 2048u), "r"(h0), "r"(h1) : "memory");
            }
        }
        __syncthreads();

        if (it < 11) stage(p + 1, buf ^ 1);   // async, overlaps MMA below

        // ---- compute: 2m x 4n frags, K = 6x16, single term ----
        float d[2][4][4];
#pragma unroll
        for (int mi = 0; mi < 2; mi++)
#pragma unroll
            for (int nj = 0; nj < 4; nj++) {
                d[mi][nj][0] = bini[mi][0];
                d[mi][nj][1] = bini[mi][0];
                d[mi][nj][2] = bini[mi][1];
                d[mi][nj][3] = bini[mi][1];
            }

#pragma unroll
        for (int kt = 0; kt < 6; kt++) {
            u32 ah[2][4];
#pragma unroll
            for (int mi = 0; mi < 2; mi++) {
                uint4 vh = ((const uint4*)(smraw + A_OFF))[(kt * 8 + mt0 + mi) * 32 + lane];
                ah[mi][0] = vh.x; ah[mi][1] = vh.y; ah[mi][2] = vh.z; ah[mi][3] = vh.w;
            }
            u32 bh[4][2];
#pragma unroll
            for (int jp = 0; jp < 2; jp++) {
                uint4 vb = ((const uint4*)(smraw + B_OFF))[(kt * 4 + nq * 2 + jp) * 32 + lane];
                bh[2 * jp][0]     = vb.x; bh[2 * jp][1]     = vb.y;
                bh[2 * jp + 1][0] = vb.z; bh[2 * jp + 1][1] = vb.w;
            }
#pragma unroll
            for (int mi = 0; mi < 2; mi++)
#pragma unroll
                for (int nj = 0; nj < 4; nj++)
                    mma16816(d[mi][nj], ah[mi], bh[nj]);
        }

        // ---- epilogue: two chunks (nj in {0,1} then {2,3}), 16KB bounce each ----
#pragma unroll
        for (int h = 0; h < 2; h++) {
            // chunk-local n index: nl = (n & 15) | (nq << 4), n = nq*32 + nj*8 + 2t
#pragma unroll
            for (int mi = 0; mi < 2; mi++)
#pragma unroll
                for (int njl = 0; njl < 2; njl++) {
                    int nj  = 2 * h + njl;
                    int m0  = mq * 32 + mi * 16 + g;
                    int nl0 = (nq << 4) + njl * 8 + 2 * t;
                    int x0 = (nl0 & 7) << 2, x1 = ((nl0 + 1) & 7) << 2;
                    Ds[nl0 * 128       + (m0 ^ x0)]       = d[mi][nj][0];
                    Ds[(nl0 + 1) * 128 + (m0 ^ x1)]       = d[mi][nj][1];
                    Ds[nl0 * 128       + ((m0 + 8) ^ x0)] = d[mi][nj][2];
                    Ds[(nl0 + 1) * 128 + ((m0 + 8) ^ x1)] = d[mi][nj][3];
                }
            __syncthreads();

            {
                const int co = tid & 63;
                const int ch = tid >> 6;
                float* orow = out + (((size_t)(b * 64 + co)) * 720 + (4 * p + r)) * 1280
                            + 2 * q0;
#pragma unroll
                for (int j = 0; j < 4; j++) {
                    int nl = ch * 8 + 2 * j;
                    int n  = (nl & 15) + 16 * h + ((nl >> 4) << 5);
                    int x0 = (nl & 7) << 2, x1 = ((nl + 1) & 7) << 2;
                    float4 v;
                    v.x = Ds[nl * 128       + (co ^ x0)];
                    v.y = Ds[nl * 128       + ((co + 64) ^ x0)];
                    v.z = Ds[(nl + 1) * 128 + (co ^ x1)];
                    v.w = Ds[(nl + 1) * 128 + ((co + 64) ^ x1)];
                    *(float4*)(orow + 2 * n) = v;
                }
            }
            if (h == 0) __syncthreads();   // Ds reads done before chunk-1 writes
        }
    }
}

extern "C" void kernel_launch(void* const* d_in, const int* in_sizes, int n_in,
                              void* d_out, int out_size)
{
    // x: 2*3*720*1280 = 5529600, w: 8*64*3*5*5 = 38400, b: 8*64 = 512
    const float* x = nullptr;
    const float* w = nullptr;
    const float* bb = nullptr;
    for (int i = 0; i < n_in; i++) {
        if (in_sizes[i] == 5529600)     x  = (const float*)d_in[i];
        else if (in_sizes[i] == 38400)  w  = (const float*)d_in[i];
        else if (in_sizes[i] == 512)    bb = (const float*)d_in[i];
    }
    float* out = (float*)d_out;

    cudaFuncSetAttribute(svc8_mma_kernel,
                         cudaFuncAttributeMaxDynamicSharedMemorySize, SMEM_BYTES);

    dim3 grid(10, 15, 8);
    svc8_mma_kernel<<<grid, 256, SMEM_BYTES>>>(x, w, bb, out);
}

// round 9
// speedup vs baseline: 3.9347x; 2.4938x over previous
#include <cuda_runtime.h>
#include <cuda_fp16.h>
#include <cstdint>

// SVC8 5x5 via warp-level mma.sync fp16 implicit GEMM (single fp16, fp32 acc).
//
// GEMM role swap (R9): M = q (64 spatial cols, ow = 2(q0+q)+c), N = co*2+c
// (128: phase c in the LSB), K = 6 taps x 16 (15 used).
//   out[co][4p+r][2(q0+q)+c] = bias[2r+c][co] + sum_k A[q][k] * W[(co,c)][k]
// With c in the n-LSB, each thread's c-fragment pair (n0, n0+1) is (c=0,c=1)
// at the same co and ADJACENT output columns -> epilogue is direct STG.64
// from fragments: no smem bounce, no extra barriers.
//
// A (x-data, row-major M64xK96 fp16, 12KB) rebuilt per iter from cp.async-
// staged raw rows (double-buffered). W (col-major N128xK96 fp16, 24KB)
// prepacked once per CTA in fragment order, nf-pairwise for LDS.128.

typedef unsigned int u32;

#define W_OFF   0                // 96 frags x 256B = 24576
#define A_OFF   24576            // 24 frags x 512B = 12288
#define RAW_OFF 36864            // 2 x 15 rows x 132 floats = 15840
#define SMEM_BYTES 52704

__device__ __forceinline__ u32 smem_u32(const void* p) {
    u32 a;
    asm("{ .reg .u64 t; cvta.to.shared.u64 t, %1; cvt.u32.u64 %0, t; }"
        : "=r"(a) : "l"(p));
    return a;
}

__device__ __forceinline__ u32 pk2(float v0, float v1) {
    __half2 h = __floats2half2_rn(v0, v1);   // v0 -> low half (even k)
    return *(u32*)&h;
}

__device__ __forceinline__ void mma16816(float* d, const u32* a, const u32* b) {
    asm volatile(
        "mma.sync.aligned.m16n8k16.row.col.f32.f16.f16.f32 "
        "{%0,%1,%2,%3}, {%4,%5,%6,%7}, {%8,%9}, {%0,%1,%2,%3};"
        : "+f"(d[0]), "+f"(d[1]), "+f"(d[2]), "+f"(d[3])
        : "r"(a[0]), "r"(a[1]), "r"(a[2]), "r"(a[3]), "r"(b[0]), "r"(b[1]));
}

__global__ void __launch_bounds__(256, 3) svc8_mma_kernel(
    const float* __restrict__ x,
    const float* __restrict__ w,
    const float* __restrict__ bias,
    float* __restrict__ out)
{
    extern __shared__ __align__(16) char smraw[];

    const int tid  = threadIdx.x;
    const int wid  = tid >> 5;
    const int lane = tid & 31;
    const int g    = lane >> 2;
    const int t    = lane & 3;

    const int q0 = blockIdx.x * 64;
    const int p0 = blockIdx.y * 12;
    const int b  = blockIdx.z >> 2;
    const int r  = blockIdx.z & 3;

    const u32 smb = smem_u32(smraw);
    const float* xb = x + (size_t)b * 3 * 720 * 1280;
    const int gc0 = 2 * q0 - 2;

    // ---- cp.async staging of 15 row segments (132 floats each) ----
    auto stage = [&](int p, int buf) {
        const u32 dst0 = smb + RAW_OFF + (u32)buf * 7920u;
#pragma unroll 2
        for (int k = tid; k < 1980; k += 256) {
            int idx = k / 132;
            int cc  = k - idx * 132;
            int ci  = idx / 5;
            int kh  = idx - ci * 5;
            int grow = 4 * p + r - 2 + kh;
            int gcol = gc0 + cc;
            bool ok = ((unsigned)grow < 720u) && ((unsigned)gcol < 1280u);
            const float* src = ok ? (xb + ((size_t)ci * 720 + grow) * 1280 + gcol) : xb;
            u32 sz = ok ? 4u : 0u;
            asm volatile("cp.async.ca.shared.global [%0], [%1], 4, %2;"
                         :: "r"(dst0 + (u32)k * 4u), "l"(src), "r"(sz) : "memory");
        }
        asm volatile("cp.async.commit_group;" ::: "memory");
    };

    // ---- W prepack (once): col-major n-frags, 96 frags, nf-pairwise ----
    // frag (kt, nf): lane (gg,tt): n = nf*8+gg -> co = n>>1, c = n&1;
    // b0 = W[n][k=2tt,2tt+1], b1 = W[n][k=2tt+8,2tt+9]
    for (int s = tid; s < 3072; s += 256) {
        int ln = s & 31, frag = s >> 5;
        int kt = frag >> 4, nf = frag & 15;
        int gg = ln >> 2, tt = ln & 3;
        int n  = nf * 8 + gg;
        int co = n >> 1, c = n & 1;
        int pi = kt & 1, off = (kt >> 1) - 1;
        int kw = 2 * off + pi - c + 2;
        float v[4] = {0.f, 0.f, 0.f, 0.f};
        if (kw >= 0 && kw < 5) {
            const float* wb = w + ((size_t)((2 * r + c) * 64 + co)) * 75 + kw;
#pragma unroll
            for (int j = 0; j < 4; j++) {
                int idx = 2 * tt + ((j >> 1) << 3) + (j & 1);
                if (idx < 15) {
                    int ci = idx / 5, kh = idx - ci * 5;
                    v[j] = wb[ci * 25 + kh * 5];
                }
            }
        }
        u32 b0 = pk2(v[0], v[1]);
        u32 b1 = pk2(v[2], v[3]);
        *(uint2*)(smraw + W_OFF + ((kt * 8 + (nf >> 1)) * 32 + ln) * 16 + (nf & 1) * 8)
            = make_uint2(b0, b1);
    }

    stage(p0, 0);   // prefill buffer 0

    // bias: per thread, nj in {0,1}: co = t + 4*(2*wid+nj); c = 0/1
    float bv[2][2];
#pragma unroll
    for (int nj = 0; nj < 2; nj++) {
        int co = t + 4 * (2 * wid + nj);
        bv[nj][0] = bias[(2 * r + 0) * 64 + co];
        bv[nj][1] = bias[(2 * r + 1) * 64 + co];
    }

    // ---- p loop ----
#pragma unroll 1
    for (int it = 0; it < 12; it++) {
        const int p   = p0 + it;
        const int buf = it & 1;

        asm volatile("cp.async.wait_group 0;" ::: "memory");
        __syncthreads();   // raw[buf] ready; all warps done with prev A reads

        // ---- A fill: x -> row-major m-frags (24 frags), 3 slots/thread ----
        {
            const float* rawb = (const float*)(smraw + RAW_OFF + buf * 7920);
#pragma unroll
            for (int s3 = 0; s3 < 3; s3++) {
                int s = tid + s3 * 256;
                int ln = s & 31, frag = s >> 5;     // frag in [0,24)
                int kt = frag >> 2, mi = frag & 3;
                int gg = ln >> 2, tt = ln & 3;
                int pi = kt & 1, off = (kt >> 1) - 1;
                const float* rp = rawb + 2 * (mi * 16 + gg + off) + pi + 2;
                float v0a = rp[(2 * tt) * 132];
                float v1a = rp[(2 * tt + 1) * 132];
                float v0b = rp[16 + (2 * tt) * 132];
                float v1b = rp[16 + (2 * tt + 1) * 132];
                float v2a = rp[(2 * tt + 8) * 132];
                float v2b = rp[16 + (2 * tt + 8) * 132];
                float v3a = (tt < 3) ? rp[(2 * tt + 9) * 132] : 0.f;
                float v3b = (tt < 3) ? rp[16 + (2 * tt + 9) * 132] : 0.f;
                uint4 av;
                av.x = pk2(v0a, v1a);    // a0: (q, k lo)
                av.y = pk2(v0b, v1b);    // a1: (q+8, k lo)
                av.z = pk2(v2a, v3a);    // a2: (q, k hi)
                av.w = pk2(v2b, v3b);    // a3: (q+8, k hi)
                ((uint4*)(smraw + A_OFF))[frag * 32 + ln] = av;
            }
        }
        __syncthreads();

        if (it < 11) stage(p + 1, buf ^ 1);   // async, overlaps MMA below

        // ---- compute: 4 m-frags x 2 n-frags, K = 6x16 ----
        float d[4][2][4];
#pragma unroll
        for (int mi = 0; mi < 4; mi++)
#pragma unroll
            for (int nj = 0; nj < 2; nj++) {
                d[mi][nj][0] = bv[nj][0];
                d[mi][nj][1] = bv[nj][1];
                d[mi][nj][2] = bv[nj][0];
                d[mi][nj][3] = bv[nj][1];
            }

#pragma unroll
        for (int kt = 0; kt < 6; kt++) {
            u32 bh[2][2];
            {
                uint4 vb = ((const uint4*)(smraw + W_OFF))[(kt * 8 + wid) * 32 + lane];
                bh[0][0] = vb.x; bh[0][1] = vb.y;
                bh[1][0] = vb.z; bh[1][1] = vb.w;
            }
#pragma unroll
            for (int mi = 0; mi < 4; mi++) {
                u32 ah[4];
                uint4 va = ((const uint4*)(smraw + A_OFF))[(kt * 4 + mi) * 32 + lane];
                ah[0] = va.x; ah[1] = va.y; ah[2] = va.z; ah[3] = va.w;
                mma16816(d[mi][0], ah, bh[0]);
                mma16816(d[mi][1], ah, bh[1]);
            }
        }

        // ---- epilogue: direct STG.64 from fragments (no bounce, no sync) ----
        {
            const int oh = 4 * p + r;
#pragma unroll
            for (int nj = 0; nj < 2; nj++) {
                int co = t + 4 * (2 * wid + nj);
                float* orow = out + (((size_t)(b * 64 + co)) * 720 + oh) * 1280
                            + 2 * q0;
#pragma unroll
                for (int mi = 0; mi < 4; mi++) {
                    int q = mi * 16 + g;
                    float2 u0 = make_float2(d[mi][nj][0], d[mi][nj][1]);
                    float2 u1 = make_float2(d[mi][nj][2], d[mi][nj][3]);
                    *(float2*)(orow + 2 * q)      = u0;
                    *(float2*)(orow + 2 * q + 16) = u1;
                }
            }
        }
    }
}

extern "C" void kernel_launch(void* const* d_in, const int* in_sizes, int n_in,
                              void* d_out, int out_size)
{
    // x: 2*3*720*1280 = 5529600, w: 8*64*3*5*5 = 38400, b: 8*64 = 512
    const float* x = nullptr;
    const float* w = nullptr;
    const float* bb = nullptr;
    for (int i = 0; i < n_in; i++) {
        if (in_sizes[i] == 5529600)     x  = (const float*)d_in[i];
        else if (in_sizes[i] == 38400)  w  = (const float*)d_in[i];
        else if (in_sizes[i] == 512)    bb = (const float*)d_in[i];
    }
    float* out = (float*)d_out;

    cudaFuncSetAttribute(svc8_mma_kernel,
                         cudaFuncAttributeMaxDynamicSharedMemorySize, SMEM_BYTES);

    dim3 grid(10, 15, 8);
    svc8_mma_kernel<<<grid, 256, SMEM_BYTES>>>(x, w, bb, out);
}

// round 10
// speedup vs baseline: 4.0745x; 1.0355x over previous
#include <cuda_runtime.h>
#include <cuda_fp16.h>
#include <cstdint>

// SVC8 5x5 via warp-level mma.sync fp16 implicit GEMM (single fp16, fp32 acc).
//
// M = q (64 spatial cols, ow = 2(q0+q)+c), N = co*2+c (128), K = 6 taps x 16.
//   out[co][4p+r][2(q0+q)+c] = bias[2r+c][co] + sum_k A[q][k] * W[(co,c)][k]
// c in the n-LSB -> thread's c-fragment pair = adjacent output cols -> direct
// STG.64 epilogue, no bounce.
//
// R10: (a) warp tile 32x32 (was 64x16): A-fragment re-read 8x -> 4x;
// (b) cp.async stages x into DEINTERLEAVED even/odd q-planes
// [pi][16 rows][68 floats] -> every A-fill LDS.32 is conflict-free
// (bank = 8*tt + gg, all distinct), and the zero pad row kills the tail guard.

typedef unsigned int u32;

#define W_OFF   0                // 96 frags x 256B = 24576
#define A_OFF   24576            // 24 frags x 512B = 12288
#define RAW_OFF 36864            // 2 bufs x 2 planes x 16 rows x 68 floats
#define PLANE_B 4352             // 16*68*4
#define BUF_B   8704
#define SMEM_BYTES 54272

__device__ __forceinline__ u32 smem_u32(const void* p) {
    u32 a;
    asm("{ .reg .u64 t; cvta.to.shared.u64 t, %1; cvt.u32.u64 %0, t; }"
        : "=r"(a) : "l"(p));
    return a;
}

__device__ __forceinline__ u32 pk2(float v0, float v1) {
    __half2 h = __floats2half2_rn(v0, v1);   // v0 -> low half (even k)
    return *(u32*)&h;
}

__device__ __forceinline__ void mma16816(float* d, const u32* a, const u32* b) {
    asm volatile(
        "mma.sync.aligned.m16n8k16.row.col.f32.f16.f16.f32 "
        "{%0,%1,%2,%3}, {%4,%5,%6,%7}, {%8,%9}, {%0,%1,%2,%3};"
        : "+f"(d[0]), "+f"(d[1]), "+f"(d[2]), "+f"(d[3])
        : "r"(a[0]), "r"(a[1]), "r"(a[2]), "r"(a[3]), "r"(b[0]), "r"(b[1]));
}

__global__ void __launch_bounds__(256, 3) svc8_mma_kernel(
    const float* __restrict__ x,
    const float* __restrict__ w,
    const float* __restrict__ bias,
    float* __restrict__ out)
{
    extern __shared__ __align__(16) char smraw[];

    const int tid  = threadIdx.x;
    const int wid  = tid >> 5;
    const int lane = tid & 31;
    const int g    = lane >> 2;
    const int t    = lane & 3;

    const int q0 = blockIdx.x * 64;
    const int p0 = blockIdx.y * 12;
    const int b  = blockIdx.z >> 2;
    const int r  = blockIdx.z & 3;

    const u32 smb = smem_u32(smraw);
    const float* xb = x + (size_t)b * 3 * 720 * 1280;
    const int gc0 = 2 * q0 - 2;

    // ---- zero the pad rows (row 15 of each plane, both buffers) ----
    for (int k = tid; k < 272; k += 256) {
        int buf = k / 136, rest = k - buf * 136;
        int pi = rest / 68, cc = rest - pi * 68;
        *(float*)(smraw + RAW_OFF + buf * BUF_B + pi * PLANE_B + (15 * 68 + cc) * 4) = 0.f;
    }

    // ---- cp.async staging: deinterleaved planes [pi][row][qrel] ----
    // element (row, cc): gcol = gc0 + cc; pi = cc&1; qrel = cc>>1 (0..65)
    auto stage = [&](int p, int buf) {
        const u32 dst0 = smb + RAW_OFF + (u32)buf * BUF_B;
#pragma unroll 2
        for (int k = tid; k < 1980; k += 256) {
            int idx = k / 132;
            int cc  = k - idx * 132;
            int ci  = idx / 5;
            int kh  = idx - ci * 5;
            int grow = 4 * p + r - 2 + kh;
            int gcol = gc0 + cc;
            bool ok = ((unsigned)grow < 720u) && ((unsigned)gcol < 1280u);
            const float* src = ok ? (xb + ((size_t)ci * 720 + grow) * 1280 + gcol) : xb;
            u32 sz = ok ? 4u : 0u;
            u32 dst = dst0 + (u32)(cc & 1) * PLANE_B
                    + (u32)(idx * 68 + (cc >> 1)) * 4u;
            asm volatile("cp.async.ca.shared.global [%0], [%1], 4, %2;"
                         :: "r"(dst), "l"(src), "r"(sz) : "memory");
        }
        asm volatile("cp.async.commit_group;" ::: "memory");
    };

    // ---- W prepack (once): col-major n-frags, 96 frags, nf-pairwise ----
    for (int s = tid; s < 3072; s += 256) {
        int ln = s & 31, frag = s >> 5;
        int kt = frag >> 4, nf = frag & 15;
        int gg = ln >> 2, tt = ln & 3;
        int n  = nf * 8 + gg;
        int co = n >> 1, c = n & 1;
        int pi = kt & 1, off = (kt >> 1) - 1;
        int kw = 2 * off + pi - c + 2;
        float v[4] = {0.f, 0.f, 0.f, 0.f};
        if (kw >= 0 && kw < 5) {
            const float* wb = w + ((size_t)((2 * r + c) * 64 + co)) * 75 + kw;
#pragma unroll
            for (int j = 0; j < 4; j++) {
                int idx = 2 * tt + ((j >> 1) << 3) + (j & 1);
                if (idx < 15) {
                    int ci = idx / 5, kh = idx - ci * 5;
                    v[j] = wb[ci * 25 + kh * 5];
                }
            }
        }
        u32 b0 = pk2(v[0], v[1]);
        u32 b1 = pk2(v[2], v[3]);
        *(uint2*)(smraw + W_OFF + ((kt * 8 + (nf >> 1)) * 32 + ln) * 16 + (nf & 1) * 8)
            = make_uint2(b0, b1);
    }

    stage(p0, 0);   // prefill buffer 0

    // ---- warp tiling 32x32: mq = wid&1 (2 m-frags), nq = wid>>1 (4 n-frags) ----
    const int mq = wid & 1, nq = wid >> 1;

    float bv[4][2];
#pragma unroll
    for (int nj = 0; nj < 4; nj++) {
        int co = (nq * 4 + nj) * 4 + t;
        bv[nj][0] = bias[(2 * r + 0) * 64 + co];
        bv[nj][1] = bias[(2 * r + 1) * 64 + co];
    }

    // ---- p loop ----
#pragma unroll 1
    for (int it = 0; it < 12; it++) {
        const int p   = p0 + it;
        const int buf = it & 1;

        asm volatile("cp.async.wait_group 0;" ::: "memory");
        __syncthreads();   // raw[buf] ready; prev A reads done

        // ---- A fill from deinterleaved planes: 24 frags, 3 slots/thread ----
        // frag (kt, mi): lane (gg,tt): q = mi*16+gg, k pair rows 2tt(+1), +8
        {
#pragma unroll
            for (int s3 = 0; s3 < 3; s3++) {
                int s = tid + s3 * 256;
                int ln = s & 31, frag = s >> 5;     // frag in [0,24)
                int kt = frag >> 2, mi = frag & 3;
                int gg = ln >> 2, tt = ln & 3;
                int pi = kt & 1, off = (kt >> 1) - 1;
                const float* pl = (const float*)(smraw + RAW_OFF + buf * BUF_B
                                                 + pi * PLANE_B);
                int cb = mi * 16 + gg + off + 1;
                const float* rp = pl + cb;
                float v0a = rp[(2 * tt) * 68];
                float v1a = rp[(2 * tt + 1) * 68];
                float v0b = rp[(2 * tt) * 68 + 8];
                float v1b = rp[(2 * tt + 1) * 68 + 8];
                float v2a = rp[(2 * tt + 8) * 68];
                float v3a = rp[(2 * tt + 9) * 68];      // row 15 = zero pad
                float v2b = rp[(2 * tt + 8) * 68 + 8];
                float v3b = rp[(2 * tt + 9) * 68 + 8];
                uint4 av;
                av.x = pk2(v0a, v1a);    // (q,   k lo)
                av.y = pk2(v0b, v1b);    // (q+8, k lo)
                av.z = pk2(v2a, v3a);    // (q,   k hi)
                av.w = pk2(v2b, v3b);    // (q+8, k hi)
                ((uint4*)(smraw + A_OFF))[frag * 32 + ln] = av;
            }
        }
        __syncthreads();

        if (it < 11) stage(p + 1, buf ^ 1);   // async, overlaps MMA below

        // ---- compute: 2 m-frags x 4 n-frags, K = 6x16 ----
        float d[2][4][4];
#pragma unroll
        for (int mi = 0; mi < 2; mi++)
#pragma unroll
            for (int nj = 0; nj < 4; nj++) {
                d[mi][nj][0] = bv[nj][0];
                d[mi][nj][1] = bv[nj][1];
                d[mi][nj][2] = bv[nj][0];
                d[mi][nj][3] = bv[nj][1];
            }

#pragma unroll
        for (int kt = 0; kt < 6; kt++) {
            u32 bh[4][2];
#pragma unroll
            for (int jp = 0; jp < 2; jp++) {
                uint4 vb = ((const uint4*)(smraw + W_OFF))[(kt * 8 + nq * 2 + jp) * 32 + lane];
                bh[2 * jp][0]     = vb.x; bh[2 * jp][1]     = vb.y;
                bh[2 * jp + 1][0] = vb.z; bh[2 * jp + 1][1] = vb.w;
            }
#pragma unroll
            for (int mi = 0; mi < 2; mi++) {
                u32 ah[4];
                uint4 va = ((const uint4*)(smraw + A_OFF))[(kt * 4 + mq * 2 + mi) * 32 + lane];
                ah[0] = va.x; ah[1] = va.y; ah[2] = va.z; ah[3] = va.w;
#pragma unroll
                for (int nj = 0; nj < 4; nj++)
                    mma16816(d[mi][nj], ah, bh[nj]);
            }
        }

        // ---- epilogue: direct STG.64 from fragments ----
        {
            const int oh = 4 * p + r;
#pragma unroll
            for (int nj = 0; nj < 4; nj++) {
                int co = (nq * 4 + nj) * 4 + t;
                float* orow = out + (((size_t)(b * 64 + co)) * 720 + oh) * 1280
                            + 2 * q0;
#pragma unroll
                for (int mi = 0; mi < 2; mi++) {
                    int q = (mq * 2 + mi) * 16 + g;
                    *(float2*)(orow + 2 * q)      = make_float2(d[mi][nj][0], d[mi][nj][1]);
                    *(float2*)(orow + 2 * q + 16) = make_float2(d[mi][nj][2], d[mi][nj][3]);
                }
            }
        }
    }
}

extern "C" void kernel_launch(void* const* d_in, const int* in_sizes, int n_in,
                              void* d_out, int out_size)
{
    // x: 2*3*720*1280 = 5529600, w: 8*64*3*5*5 = 38400, b: 8*64 = 512
    const float* x = nullptr;
    const float* w = nullptr;
    const float* bb = nullptr;
    for (int i = 0; i < n_in; i++) {
        if (in_sizes[i] == 5529600)     x  = (const float*)d_in[i];
        else if (in_sizes[i] == 38400)  w  = (const float*)d_in[i];
        else if (in_sizes[i] == 512)    bb = (const float*)d_in[i];
    }
    float* out = (float*)d_out;

    cudaFuncSetAttribute(svc8_mma_kernel,
                         cudaFuncAttributeMaxDynamicSharedMemorySize, SMEM_BYTES);

    dim3 grid(10, 15, 8);
    svc8_mma_kernel<<<grid, 256, SMEM_BYTES>>>(x, w, bb, out);
}

// round 12
// speedup vs baseline: 4.3655x; 1.0714x over previous
#include <cuda_runtime.h>
#include <cuda_fp16.h>
#include <cstdint>

// SVC8 5x5 via warp-level mma.sync fp16 implicit GEMM (single fp16, fp32 acc).
//
// M = q (64 spatial cols, ow = 2(q0+q)+c), N = co*2+c (128), K = 6 taps x 16.
//   out[co][4p+r][2(q0+q)+c] = bias[2r+c][co] + sum_k A[q][k] * W[(co,c)][k]
// c in the n-LSB -> thread's c-fragment pair = adjacent output cols -> direct
// STG.64 epilogue, no bounce.
//
// R12: R11 (16B cp.async staging into interleaved 140-float-stride rows,
// float2 A-fill reads, early stage issue) with the q+8 indexing bug fixed:
// in the interleaved layout one float2 = one q position, so q+8 = +8 float2
// (R11 wrongly used +4, copied from the deinterleaved float-plane layout).

typedef unsigned int u32;

#define W_OFF   0                // 96 frags x 256B = 24576
#define A_OFF   24576            // 24 frags x 512B = 12288
#define RAW_OFF 36864            // 2 bufs x 16 rows x 140 floats (560B rows)
#define ROW_B   560
#define BUF_B   8960
#define SMEM_BYTES 54784

__device__ __forceinline__ u32 smem_u32(const void* p) {
    u32 a;
    asm("{ .reg .u64 t; cvta.to.shared.u64 t, %1; cvt.u32.u64 %0, t; }"
        : "=r"(a) : "l"(p));
    return a;
}

__device__ __forceinline__ u32 pk2(float v0, float v1) {
    __half2 h = __floats2half2_rn(v0, v1);   // v0 -> low half (even k)
    return *(u32*)&h;
}

__device__ __forceinline__ void mma16816(float* d, const u32* a, const u32* b) {
    asm volatile(
        "mma.sync.aligned.m16n8k16.row.col.f32.f16.f16.f32 "
        "{%0,%1,%2,%3}, {%4,%5,%6,%7}, {%8,%9}, {%0,%1,%2,%3};"
        : "+f"(d[0]), "+f"(d[1]), "+f"(d[2]), "+f"(d[3])
        : "r"(a[0]), "r"(a[1]), "r"(a[2]), "r"(a[3]), "r"(b[0]), "r"(b[1]));
}

__global__ void __launch_bounds__(256, 3) svc8_mma_kernel(
    const float* __restrict__ x,
    const float* __restrict__ w,
    const float* __restrict__ bias,
    float* __restrict__ out)
{
    extern __shared__ __align__(16) char smraw[];

    const int tid  = threadIdx.x;
    const int wid  = tid >> 5;
    const int lane = tid & 31;
    const int g    = lane >> 2;
    const int t    = lane & 3;

    const int q0 = blockIdx.x * 64;
    const int p0 = blockIdx.y * 12;
    const int b  = blockIdx.z >> 2;
    const int r  = blockIdx.z & 3;

    const u32 smb = smem_u32(smraw);
    const float* xb = x + (size_t)b * 3 * 720 * 1280;
    const int gcA = 2 * q0 - 4;          // 16B-aligned staging origin

    // ---- zero pad row 15 of both buffers (140 floats each) ----
    for (int k = tid; k < 280; k += 256) {
        int buf = k / 140, cc = k - buf * 140;
        *(float*)(smraw + RAW_OFF + buf * BUF_B + 15 * ROW_B + cc * 4) = 0.f;
    }

    // ---- cp.async staging: 15 rows x 34 x 16B granules, interleaved ----
    // granule (idx, m): gcol0 = gcA + 4m; fully in- or out-of-bounds at edges.
    auto stage = [&](int p, int buf) {
        const u32 dst0 = smb + RAW_OFF + (u32)buf * BUF_B;
#pragma unroll
        for (int j = 0; j < 2; j++) {
            int s = tid + j * 256;
            if (s < 510) {
                int idx = s / 34;
                int m   = s - idx * 34;
                int ci  = idx / 5;
                int kh  = idx - ci * 5;
                int grow  = 4 * p + r - 2 + kh;
                int gcol0 = gcA + 4 * m;
                bool ok = ((unsigned)grow < 720u) && ((unsigned)gcol0 < 1277u);
                const float* src = ok ? (xb + ((size_t)ci * 720 + grow) * 1280 + gcol0)
                                      : xb;
                u32 sz = ok ? 16u : 0u;
                asm volatile("cp.async.ca.shared.global [%0], [%1], 16, %2;"
                             :: "r"(dst0 + (u32)idx * ROW_B + (u32)m * 16u),
                                "l"(src), "r"(sz) : "memory");
            }
        }
        asm volatile("cp.async.commit_group;" ::: "memory");
    };

    // ---- W prepack (once): col-major n-frags, 96 frags, nf-pairwise ----
    for (int s = tid; s < 3072; s += 256) {
        int ln = s & 31, frag = s >> 5;
        int kt = frag >> 4, nf = frag & 15;
        int gg = ln >> 2, tt = ln & 3;
        int n  = nf * 8 + gg;
        int co = n >> 1, c = n & 1;
        int pi = kt & 1, off = (kt >> 1) - 1;
        int kw = 2 * off + pi - c + 2;
        float v[4] = {0.f, 0.f, 0.f, 0.f};
        if (kw >= 0 && kw < 5) {
            const float* wb = w + ((size_t)((2 * r + c) * 64 + co)) * 75 + kw;
#pragma unroll
            for (int j = 0; j < 4; j++) {
                int idx = 2 * tt + ((j >> 1) << 3) + (j & 1);
                if (idx < 15) {
                    int ci = idx / 5, kh = idx - ci * 5;
                    v[j] = wb[ci * 25 + kh * 5];
                }
            }
        }
        u32 b0 = pk2(v[0], v[1]);
        u32 b1 = pk2(v[2], v[3]);
        *(uint2*)(smraw + W_OFF + ((kt * 8 + (nf >> 1)) * 32 + ln) * 16 + (nf & 1) * 8)
            = make_uint2(b0, b1);
    }

    stage(p0, 0);   // prefill buffer 0

    // ---- warp tiling 32x32: mq = wid&1 (2 m-frags), nq = wid>>1 (4 n-frags) ----
    const int mq = wid & 1, nq = wid >> 1;

    float bv[4][2];
#pragma unroll
    for (int nj = 0; nj < 4; nj++) {
        int co = (nq * 4 + nj) * 4 + t;
        bv[nj][0] = bias[(2 * r + 0) * 64 + co];
        bv[nj][1] = bias[(2 * r + 1) * 64 + co];
    }

    // ---- p loop ----
#pragma unroll 1
    for (int it = 0; it < 12; it++) {
        const int p   = p0 + it;
        const int buf = it & 1;

        asm volatile("cp.async.wait_group 0;" ::: "memory");
        __syncthreads();   // raw[buf] ready; prev A reads done

        // next-iter staging first: overlaps A-fill + MMA + epilogue.
        // buf^1's last readers were iter it-1's A-fill, already complete.
        if (it < 11) stage(p + 1, buf ^ 1);

        // ---- A fill from interleaved rows: 24 frags, 3 slots/thread ----
        // frag (kt, mi): lane (gg,tt): q = mi*16+gg; float2 col = q+off+2,
        // component pi. Rows 2tt, 2tt+1, 2tt+8, 2tt+9 (row 15 = zero pad).
        // One float2 = one q position -> q+8 is +8 float2.
        {
            const float2* pl = (const float2*)(smraw + RAW_OFF + buf * BUF_B);
#pragma unroll
            for (int s3 = 0; s3 < 3; s3++) {
                int s = tid + s3 * 256;
                int ln = s & 31, frag = s >> 5;     // frag in [0,24)
                int kt = frag >> 2, mi = frag & 3;
                int gg = ln >> 2, tt = ln & 3;
                int pi = kt & 1, off = (kt >> 1) - 1;
                const float2* rp = pl + (mi * 16 + gg + off + 2);   // 70 f2/row
                float2 w0a = rp[(2 * tt) * 70];
                float2 w1a = rp[(2 * tt + 1) * 70];
                float2 w0b = rp[(2 * tt) * 70 + 8];
                float2 w1b = rp[(2 * tt + 1) * 70 + 8];
                float2 w2a = rp[(2 * tt + 8) * 70];
                float2 w3a = rp[(2 * tt + 9) * 70];
                float2 w2b = rp[(2 * tt + 8) * 70 + 8];
                float2 w3b = rp[(2 * tt + 9) * 70 + 8];
                float v0a = pi ? w0a.y : w0a.x;
                float v1a = pi ? w1a.y : w1a.x;
                float v0b = pi ? w0b.y : w0b.x;
                float v1b = pi ? w1b.y : w1b.x;
                float v2a = pi ? w2a.y : w2a.x;
                float v3a = pi ? w3a.y : w3a.x;
                float v2b = pi ? w2b.y : w2b.x;
                float v3b = pi ? w3b.y : w3b.x;
                uint4 av;
                av.x = pk2(v0a, v1a);    // (q,   k lo)
                av.y = pk2(v0b, v1b);    // (q+8, k lo)
                av.z = pk2(v2a, v3a);    // (q,   k hi)
                av.w = pk2(v2b, v3b);    // (q+8, k hi)
                ((uint4*)(smraw + A_OFF))[frag * 32 + ln] = av;
            }
        }
        __syncthreads();

        // ---- compute: 2 m-frags x 4 n-frags, K = 6x16 ----
        float d[2][4][4];
#pragma unroll
        for (int mi = 0; mi < 2; mi++)
#pragma unroll
            for (int nj = 0; nj < 4; nj++) {
                d[mi][nj][0] = bv[nj][0];
                d[mi][nj][1] = bv[nj][1];
                d[mi][nj][2] = bv[nj][0];
                d[mi][nj][3] = bv[nj][1];
            }

#pragma unroll
        for (int kt = 0; kt < 6; kt++) {
            u32 bh[4][2];
#pragma unroll
            for (int jp = 0; jp < 2; jp++) {
                uint4 vb = ((const uint4*)(smraw + W_OFF))[(kt * 8 + nq * 2 + jp) * 32 + lane];
                bh[2 * jp][0]     = vb.x; bh[2 * jp][1]     = vb.y;
                bh[2 * jp + 1][0] = vb.z; bh[2 * jp + 1][1] = vb.w;
            }
#pragma unroll
            for (int mi = 0; mi < 2; mi++) {
                u32 ah[4];
                uint4 va = ((const uint4*)(smraw + A_OFF))[(kt * 4 + mq * 2 + mi) * 32 + lane];
                ah[0] = va.x; ah[1] = va.y; ah[2] = va.z; ah[3] = va.w;
#pragma unroll
                for (int nj = 0; nj < 4; nj++)
                    mma16816(d[mi][nj], ah, bh[nj]);
            }
        }

        // ---- epilogue: direct STG.64 from fragments ----
        {
            const int oh = 4 * p + r;
#pragma unroll
            for (int nj = 0; nj < 4; nj++) {
                int co = (nq * 4 + nj) * 4 + t;
                float* orow = out + (((size_t)(b * 64 + co)) * 720 + oh) * 1280
                            + 2 * q0;
#pragma unroll
                for (int mi = 0; mi < 2; mi++) {
                    int q = (mq * 2 + mi) * 16 + g;
                    *(float2*)(orow + 2 * q)      = make_float2(d[mi][nj][0], d[mi][nj][1]);
                    *(float2*)(orow + 2 * q + 16) = make_float2(d[mi][nj][2], d[mi][nj][3]);
                }
            }
        }
    }
}

extern "C" void kernel_launch(void* const* d_in, const int* in_sizes, int n_in,
                              void* d_out, int out_size)
{
    // x: 2*3*720*1280 = 5529600, w: 8*64*3*5*5 = 38400, b: 8*64 = 512
    const float* x = nullptr;
    const float* w = nullptr;
    const float* bb = nullptr;
    for (int i = 0; i < n_in; i++) {
        if (in_sizes[i] == 5529600)     x  = (const float*)d_in[i];
        else if (in_sizes[i] == 38400)  w  = (const float*)d_in[i];
        else if (in_sizes[i] == 512)    bb = (const float*)d_in[i];
    }
    float* out = (float*)d_out;

    cudaFuncSetAttribute(svc8_mma_kernel,
                         cudaFuncAttributeMaxDynamicSharedMemorySize, SMEM_BYTES);

    dim3 grid(10, 15, 8);
    svc8_mma_kernel<<<grid, 256, SMEM_BYTES>>>(x, w, bb, out);
}

// round 13
// speedup vs baseline: 4.9776x; 1.1402x over previous
#include <cuda_runtime.h>
#include <cuda_fp16.h>
#include <cstdint>

// SVC8 5x5 via warp-level mma.sync fp16 implicit GEMM (single fp16, fp32 acc).
//
// M = q (64 spatial cols, ow = 2(q0+q)+c), N = co*2+c (128), K = 6 taps x 16.
//   out[co][4p+r][2(q0+q)+c] = bias[2r+c][co] + sum_k A[q][k] * W[(co,c)][k]
// c in the n-LSB -> thread's c-fragment pair = adjacent output cols -> direct
// STG.64 epilogue, no bounce.
//
// R13: W fragments are loop-invariant -> hoisted into registers once per warp
// (12 x uint4 = 48 regs), deleting 384 L1 wavefronts/iter (21% of all L1
// work) from the mainloop. 2 CTAs/SM (reg cap 128). Rest identical to R12:
// 16B cp.async staging into interleaved 140-float-stride rows, conflict-free
// float2 A-fill, direct-STG epilogue.

typedef unsigned int u32;

#define W_OFF   0                // 96 frags x 256B = 24576
#define A_OFF   24576            // 24 frags x 512B = 12288
#define RAW_OFF 36864            // 2 bufs x 16 rows x 140 floats (560B rows)
#define ROW_B   560
#define BUF_B   8960
#define SMEM_BYTES 54784

__device__ __forceinline__ u32 smem_u32(const void* p) {
    u32 a;
    asm("{ .reg .u64 t; cvta.to.shared.u64 t, %1; cvt.u32.u64 %0, t; }"
        : "=r"(a) : "l"(p));
    return a;
}

__device__ __forceinline__ u32 pk2(float v0, float v1) {
    __half2 h = __floats2half2_rn(v0, v1);   // v0 -> low half (even k)
    return *(u32*)&h;
}

__device__ __forceinline__ void mma16816(float* d, const u32* a, const u32* b) {
    asm volatile(
        "mma.sync.aligned.m16n8k16.row.col.f32.f16.f16.f32 "
        "{%0,%1,%2,%3}, {%4,%5,%6,%7}, {%8,%9}, {%0,%1,%2,%3};"
        : "+f"(d[0]), "+f"(d[1]), "+f"(d[2]), "+f"(d[3])
        : "r"(a[0]), "r"(a[1]), "r"(a[2]), "r"(a[3]), "r"(b[0]), "r"(b[1]));
}

__global__ void __launch_bounds__(256, 2) svc8_mma_kernel(
    const float* __restrict__ x,
    const float* __restrict__ w,
    const float* __restrict__ bias,
    float* __restrict__ out)
{
    extern __shared__ __align__(16) char smraw[];

    const int tid  = threadIdx.x;
    const int wid  = tid >> 5;
    const int lane = tid & 31;
    const int g    = lane >> 2;
    const int t    = lane & 3;

    const int q0 = blockIdx.x * 64;
    const int p0 = blockIdx.y * 12;
    const int b  = blockIdx.z >> 2;
    const int r  = blockIdx.z & 3;

    const u32 smb = smem_u32(smraw);
    const float* xb = x + (size_t)b * 3 * 720 * 1280;
    const int gcA = 2 * q0 - 4;          // 16B-aligned staging origin

    // ---- zero pad row 15 of both buffers (140 floats each) ----
    for (int k = tid; k < 280; k += 256) {
        int buf = k / 140, cc = k - buf * 140;
        *(float*)(smraw + RAW_OFF + buf * BUF_B + 15 * ROW_B + cc * 4) = 0.f;
    }

    // ---- cp.async staging: 15 rows x 34 x 16B granules, interleaved ----
    auto stage = [&](int p, int buf) {
        const u32 dst0 = smb + RAW_OFF + (u32)buf * BUF_B;
#pragma unroll
        for (int j = 0; j < 2; j++) {
            int s = tid + j * 256;
            if (s < 510) {
                int idx = s / 34;
                int m   = s - idx * 34;
                int ci  = idx / 5;
                int kh  = idx - ci * 5;
                int grow  = 4 * p + r - 2 + kh;
                int gcol0 = gcA + 4 * m;
                bool ok = ((unsigned)grow < 720u) && ((unsigned)gcol0 < 1277u);
                const float* src = ok ? (xb + ((size_t)ci * 720 + grow) * 1280 + gcol0)
                                      : xb;
                u32 sz = ok ? 16u : 0u;
                asm volatile("cp.async.ca.shared.global [%0], [%1], 16, %2;"
                             :: "r"(dst0 + (u32)idx * ROW_B + (u32)m * 16u),
                                "l"(src), "r"(sz) : "memory");
            }
        }
        asm volatile("cp.async.commit_group;" ::: "memory");
    };

    // ---- W prepack (once): col-major n-frags, 96 frags, nf-pairwise ----
    for (int s = tid; s < 3072; s += 256) {
        int ln = s & 31, frag = s >> 5;
        int kt = frag >> 4, nf = frag & 15;
        int gg = ln >> 2, tt = ln & 3;
        int n  = nf * 8 + gg;
        int co = n >> 1, c = n & 1;
        int pi = kt & 1, off = (kt >> 1) - 1;
        int kw = 2 * off + pi - c + 2;
        float v[4] = {0.f, 0.f, 0.f, 0.f};
        if (kw >= 0 && kw < 5) {
            const float* wb = w + ((size_t)((2 * r + c) * 64 + co)) * 75 + kw;
#pragma unroll
            for (int j = 0; j < 4; j++) {
                int idx = 2 * tt + ((j >> 1) << 3) + (j & 1);
                if (idx < 15) {
                    int ci = idx / 5, kh = idx - ci * 5;
                    v[j] = wb[ci * 25 + kh * 5];
                }
            }
        }
        u32 b0 = pk2(v[0], v[1]);
        u32 b1 = pk2(v[2], v[3]);
        *(uint2*)(smraw + W_OFF + ((kt * 8 + (nf >> 1)) * 32 + ln) * 16 + (nf & 1) * 8)
            = make_uint2(b0, b1);
    }

    stage(p0, 0);   // prefill buffer 0
    __syncthreads();   // W tile complete

    // ---- warp tiling 32x32: mq = wid&1 (2 m-frags), nq = wid>>1 (4 n-frags) ----
    const int mq = wid & 1, nq = wid >> 1;

    // ---- hoist W fragments into registers (loop-invariant) ----
    uint4 wreg[6][2];
#pragma unroll
    for (int kt = 0; kt < 6; kt++)
#pragma unroll
        for (int jp = 0; jp < 2; jp++)
            wreg[kt][jp] = ((const uint4*)(smraw + W_OFF))[(kt * 8 + nq * 2 + jp) * 32 + lane];

    float bv[4][2];
#pragma unroll
    for (int nj = 0; nj < 4; nj++) {
        int co = (nq * 4 + nj) * 4 + t;
        bv[nj][0] = bias[(2 * r + 0) * 64 + co];
        bv[nj][1] = bias[(2 * r + 1) * 64 + co];
    }

    // ---- p loop ----
#pragma unroll 1
    for (int it = 0; it < 12; it++) {
        const int p   = p0 + it;
        const int buf = it & 1;

        asm volatile("cp.async.wait_group 0;" ::: "memory");
        __syncthreads();   // raw[buf] ready; prev A reads done

        // next-iter staging first: overlaps A-fill + MMA + epilogue
        if (it < 11) stage(p + 1, buf ^ 1);

        // ---- A fill from interleaved rows: 24 frags, 3 slots/thread ----
        {
            const float2* pl = (const float2*)(smraw + RAW_OFF + buf * BUF_B);
#pragma unroll
            for (int s3 = 0; s3 < 3; s3++) {
                int s = tid + s3 * 256;
                int ln = s & 31, frag = s >> 5;     // frag in [0,24)
                int kt = frag >> 2, mi = frag & 3;
                int gg = ln >> 2, tt = ln & 3;
                int pi = kt & 1, off = (kt >> 1) - 1;
                const float2* rp = pl + (mi * 16 + gg + off + 2);   // 70 f2/row
                float2 w0a = rp[(2 * tt) * 70];
                float2 w1a = rp[(2 * tt + 1) * 70];
                float2 w0b = rp[(2 * tt) * 70 + 8];
                float2 w1b = rp[(2 * tt + 1) * 70 + 8];
                float2 w2a = rp[(2 * tt + 8) * 70];
                float2 w3a = rp[(2 * tt + 9) * 70];
                float2 w2b = rp[(2 * tt + 8) * 70 + 8];
                float2 w3b = rp[(2 * tt + 9) * 70 + 8];
                float v0a = pi ? w0a.y : w0a.x;
                float v1a = pi ? w1a.y : w1a.x;
                float v0b = pi ? w0b.y : w0b.x;
                float v1b = pi ? w1b.y : w1b.x;
                float v2a = pi ? w2a.y : w2a.x;
                float v3a = pi ? w3a.y : w3a.x;
                float v2b = pi ? w2b.y : w2b.x;
                float v3b = pi ? w3b.y : w3b.x;
                uint4 av;
                av.x = pk2(v0a, v1a);    // (q,   k lo)
                av.y = pk2(v0b, v1b);    // (q+8, k lo)
                av.z = pk2(v2a, v3a);    // (q,   k hi)
                av.w = pk2(v2b, v3b);    // (q+8, k hi)
                ((uint4*)(smraw + A_OFF))[frag * 32 + ln] = av;
            }
        }
        __syncthreads();

        // ---- compute: 2 m-frags x 4 n-frags, K = 6x16, W in registers ----
        float d[2][4][4];
#pragma unroll
        for (int mi = 0; mi < 2; mi++)
#pragma unroll
            for (int nj = 0; nj < 4; nj++) {
                d[mi][nj][0] = bv[nj][0];
                d[mi][nj][1] = bv[nj][1];
                d[mi][nj][2] = bv[nj][0];
                d[mi][nj][3] = bv[nj][1];
            }

#pragma unroll
        for (int kt = 0; kt < 6; kt++) {
            u32 bh[4][2];
            bh[0][0] = wreg[kt][0].x; bh[0][1] = wreg[kt][0].y;
            bh[1][0] = wreg[kt][0].z; bh[1][1] = wreg[kt][0].w;
            bh[2][0] = wreg[kt][1].x; bh[2][1] = wreg[kt][1].y;
            bh[3][0] = wreg[kt][1].z; bh[3][1] = wreg[kt][1].w;
#pragma unroll
            for (int mi = 0; mi < 2; mi++) {
                u32 ah[4];
                uint4 va = ((const uint4*)(smraw + A_OFF))[(kt * 4 + mq * 2 + mi) * 32 + lane];
                ah[0] = va.x; ah[1] = va.y; ah[2] = va.z; ah[3] = va.w;
#pragma unroll
                for (int nj = 0; nj < 4; nj++)
                    mma16816(d[mi][nj], ah, bh[nj]);
            }
        }

        // ---- epilogue: direct STG.64 from fragments ----
        {
            const int oh = 4 * p + r;
#pragma unroll
            for (int nj = 0; nj < 4; nj++) {
                int co = (nq * 4 + nj) * 4 + t;
                float* orow = out + (((size_t)(b * 64 + co)) * 720 + oh) * 1280
                            + 2 * q0;
#pragma unroll
                for (int mi = 0; mi < 2; mi++) {
                    int q = (mq * 2 + mi) * 16 + g;
                    *(float2*)(orow + 2 * q)      = make_float2(d[mi][nj][0], d[mi][nj][1]);
                    *(float2*)(orow + 2 * q + 16) = make_float2(d[mi][nj][2], d[mi][nj][3]);
                }
            }
        }
    }
}

extern "C" void kernel_launch(void* const* d_in, const int* in_sizes, int n_in,
                              void* d_out, int out_size)
{
    // x: 2*3*720*1280 = 5529600, w: 8*64*3*5*5 = 38400, b: 8*64 = 512
    const float* x = nullptr;
    const float* w = nullptr;
    const float* bb = nullptr;
    for (int i = 0; i < n_in; i++) {
        if (in_sizes[i] == 5529600)     x  = (const float*)d_in[i];
        else if (in_sizes[i] == 38400)  w  = (const float*)d_in[i];
        else if (in_sizes[i] == 512)    bb = (const float*)d_in[i];
    }
    float* out = (float*)d_out;

    cudaFuncSetAttribute(svc8_mma_kernel,
                         cudaFuncAttributeMaxDynamicSharedMemorySize, SMEM_BYTES);

    dim3 grid(10, 15, 8);
    svc8_mma_kernel<<<grid, 256, SMEM_BYTES>>>(x, w, bb, out);
}

// round 14
// speedup vs baseline: 5.2842x; 1.0616x over previous
#include <cuda_runtime.h>
#include <cuda_fp16.h>
#include <cstdint>

// SVC8 5x5 via warp-level mma.sync fp16 implicit GEMM (single fp16, fp32 acc).
//
// M = q (64 spatial cols, ow = 2(q0+q)+c), N = co*2+c (128), K = 6 taps x 16.
//   out[co][4p+r][2(q0+q)+c] = bias[2r+c][co] + sum_k A[q][k] * W[(co,c)][k]
// c in the n-LSB -> thread's c-fragment pair = adjacent output cols -> direct
// STG.64 epilogue, no bounce.
//
// R14: paired A-fill. Frags kt=2*ktp (pi=0) and kt=2*ktp+1 (pi=1) need the
// two components of the SAME float2s, so one unit builds both from 8 shared
// LDS.64 -> A-fill load wavefronts halve (384 -> 192 per CTA-iter; before,
// half of every loaded float2 was discarded). 384 units over 256 threads
// (warps 0-3 take two). W fragments register-hoisted (R13); 16B cp.async
// staging into interleaved 140-float-stride rows (R12); direct-STG epilogue.

typedef unsigned int u32;

#define W_OFF   0                // 96 frags x 256B = 24576
#define A_OFF   24576            // 24 frags x 512B = 12288
#define RAW_OFF 36864            // 2 bufs x 16 rows x 140 floats (560B rows)
#define ROW_B   560
#define BUF_B   8960
#define SMEM_BYTES 54784

__device__ __forceinline__ u32 smem_u32(const void* p) {
    u32 a;
    asm("{ .reg .u64 t; cvta.to.shared.u64 t, %1; cvt.u32.u64 %0, t; }"
        : "=r"(a) : "l"(p));
    return a;
}

__device__ __forceinline__ u32 pk2(float v0, float v1) {
    __half2 h = __floats2half2_rn(v0, v1);   // v0 -> low half (even k)
    return *(u32*)&h;
}

__device__ __forceinline__ void mma16816(float* d, const u32* a, const u32* b) {
    asm volatile(
        "mma.sync.aligned.m16n8k16.row.col.f32.f16.f16.f32 "
        "{%0,%1,%2,%3}, {%4,%5,%6,%7}, {%8,%9}, {%0,%1,%2,%3};"
        : "+f"(d[0]), "+f"(d[1]), "+f"(d[2]), "+f"(d[3])
        : "r"(a[0]), "r"(a[1]), "r"(a[2]), "r"(a[3]), "r"(b[0]), "r"(b[1]));
}

__global__ void __launch_bounds__(256, 2) svc8_mma_kernel(
    const float* __restrict__ x,
    const float* __restrict__ w,
    const float* __restrict__ bias,
    float* __restrict__ out)
{
    extern __shared__ __align__(16) char smraw[];

    const int tid  = threadIdx.x;
    const int wid  = tid >> 5;
    const int lane = tid & 31;
    const int g    = lane >> 2;
    const int t    = lane & 3;

    const int q0 = blockIdx.x * 64;
    const int p0 = blockIdx.y * 12;
    const int b  = blockIdx.z >> 2;
    const int r  = blockIdx.z & 3;

    const u32 smb = smem_u32(smraw);
    const float* xb = x + (size_t)b * 3 * 720 * 1280;
    const int gcA = 2 * q0 - 4;          // 16B-aligned staging origin

    // ---- zero pad row 15 of both buffers (140 floats each) ----
    for (int k = tid; k < 280; k += 256) {
        int buf = k / 140, cc = k - buf * 140;
        *(float*)(smraw + RAW_OFF + buf * BUF_B + 15 * ROW_B + cc * 4) = 0.f;
    }

    // ---- cp.async staging: 15 rows x 34 x 16B granules, interleaved ----
    auto stage = [&](int p, int buf) {
        const u32 dst0 = smb + RAW_OFF + (u32)buf * BUF_B;
#pragma unroll
        for (int j = 0; j < 2; j++) {
            int s = tid + j * 256;
            if (s < 510) {
                int idx = s / 34;
                int m   = s - idx * 34;
                int ci  = idx / 5;
                int kh  = idx - ci * 5;
                int grow  = 4 * p + r - 2 + kh;
                int gcol0 = gcA + 4 * m;
                bool ok = ((unsigned)grow < 720u) && ((unsigned)gcol0 < 1277u);
                const float* src = ok ? (xb + ((size_t)ci * 720 + grow) * 1280 + gcol0)
                                      : xb;
                u32 sz = ok ? 16u : 0u;
                asm volatile("cp.async.ca.shared.global [%0], [%1], 16, %2;"
                             :: "r"(dst0 + (u32)idx * ROW_B + (u32)m * 16u),
                                "l"(src), "r"(sz) : "memory");
            }
        }
        asm volatile("cp.async.commit_group;" ::: "memory");
    };

    // ---- W prepack (once): col-major n-frags, 96 frags, nf-pairwise ----
    for (int s = tid; s < 3072; s += 256) {
        int ln = s & 31, frag = s >> 5;
        int kt = frag >> 4, nf = frag & 15;
        int gg = ln >> 2, tt = ln & 3;
        int n  = nf * 8 + gg;
        int co = n >> 1, c = n & 1;
        int pi = kt & 1, off = (kt >> 1) - 1;
        int kw = 2 * off + pi - c + 2;
        float v[4] = {0.f, 0.f, 0.f, 0.f};
        if (kw >= 0 && kw < 5) {
            const float* wb = w + ((size_t)((2 * r + c) * 64 + co)) * 75 + kw;
#pragma unroll
            for (int j = 0; j < 4; j++) {
                int idx = 2 * tt + ((j >> 1) << 3) + (j & 1);
                if (idx < 15) {
                    int ci = idx / 5, kh = idx - ci * 5;
                    v[j] = wb[ci * 25 + kh * 5];
                }
            }
        }
        u32 b0 = pk2(v[0], v[1]);
        u32 b1 = pk2(v[2], v[3]);
        *(uint2*)(smraw + W_OFF + ((kt * 8 + (nf >> 1)) * 32 + ln) * 16 + (nf & 1) * 8)
            = make_uint2(b0, b1);
    }

    stage(p0, 0);   // prefill buffer 0
    __syncthreads();   // W tile complete

    // ---- warp tiling 32x32: mq = wid&1 (2 m-frags), nq = wid>>1 (4 n-frags) ----
    const int mq = wid & 1, nq = wid >> 1;

    // ---- hoist W fragments into registers (loop-invariant) ----
    uint4 wreg[6][2];
#pragma unroll
    for (int kt = 0; kt < 6; kt++)
#pragma unroll
        for (int jp = 0; jp < 2; jp++)
            wreg[kt][jp] = ((const uint4*)(smraw + W_OFF))[(kt * 8 + nq * 2 + jp) * 32 + lane];

    float bv[4][2];
#pragma unroll
    for (int nj = 0; nj < 4; nj++) {
        int co = (nq * 4 + nj) * 4 + t;
        bv[nj][0] = bias[(2 * r + 0) * 64 + co];
        bv[nj][1] = bias[(2 * r + 1) * 64 + co];
    }

    // ---- p loop ----
#pragma unroll 1
    for (int it = 0; it < 12; it++) {
        const int p   = p0 + it;
        const int buf = it & 1;

        asm volatile("cp.async.wait_group 0;" ::: "memory");
        __syncthreads();   // raw[buf] ready; prev A reads done

        // next-iter staging first: overlaps A-fill + MMA + epilogue
        if (it < 11) stage(p + 1, buf ^ 1);

        // ---- paired A fill: unit u builds BOTH pi-frags of (ktp, mi) ----
        // u in [0,384): ln = u&31, pu = u>>5 in [0,12): ktp = pu>>2, mi = pu&3.
        // 8 shared LDS.64 (rows 2tt,2tt+1,2tt+8,2tt+9 x cols cb,cb+8) yield
        // frag kt=2ktp (x comps) and kt=2ktp+1 (y comps).
        {
            const float2* pl = (const float2*)(smraw + RAW_OFF + buf * BUF_B);
#pragma unroll
            for (int uu = 0; uu < 2; uu++) {
                if (uu == 0 || tid < 128) {
                    int u  = tid + uu * 256;
                    int ln = u & 31, pu = u >> 5;       // pu in [0,12)
                    int ktp = pu >> 2, mi = pu & 3;     // off = ktp - 1
                    int gg = ln >> 2, tt = ln & 3;
                    const float2* rp = pl + (mi * 16 + gg + ktp + 1);  // 70 f2/row
                    float2 a0 = rp[(2 * tt) * 70];
                    float2 a1 = rp[(2 * tt + 1) * 70];
                    float2 b0 = rp[(2 * tt) * 70 + 8];
                    float2 b1 = rp[(2 * tt + 1) * 70 + 8];
                    float2 c0 = rp[(2 * tt + 8) * 70];
                    float2 c1 = rp[(2 * tt + 9) * 70];      // row 15 = zero pad
                    float2 e0 = rp[(2 * tt + 8) * 70 + 8];
                    float2 e1 = rp[(2 * tt + 9) * 70 + 8];
                    uint4 av0, av1;
                    av0.x = pk2(a0.x, a1.x);  av1.x = pk2(a0.y, a1.y);  // (q,   k lo)
                    av0.y = pk2(b0.x, b1.x);  av1.y = pk2(b0.y, b1.y);  // (q+8, k lo)
                    av0.z = pk2(c0.x, c1.x);  av1.z = pk2(c0.y, c1.y);  // (q,   k hi)
                    av0.w = pk2(e0.x, e1.x);  av1.w = pk2(e0.y, e1.y);  // (q+8, k hi)
                    int f0 = (2 * ktp) * 4 + mi;
                    ((uint4*)(smraw + A_OFF))[f0 * 32 + ln]       = av0;
                    ((uint4*)(smraw + A_OFF))[(f0 + 4) * 32 + ln] = av1;
                }
            }
        }
        __syncthreads();

        // ---- compute: 2 m-frags x 4 n-frags, K = 6x16, W in registers ----
        float d[2][4][4];
#pragma unroll
        for (int mi = 0; mi < 2; mi++)
#pragma unroll
            for (int nj = 0; nj < 4; nj++) {
                d[mi][nj][0] = bv[nj][0];
                d[mi][nj][1] = bv[nj][1];
                d[mi][nj][2] = bv[nj][0];
                d[mi][nj][3] = bv[nj][1];
            }

#pragma unroll
        for (int kt = 0; kt < 6; kt++) {
            u32 bh[4][2];
            bh[0][0] = wreg[kt][0].x; bh[0][1] = wreg[kt][0].y;
            bh[1][0] = wreg[kt][0].z; bh[1][1] = wreg[kt][0].w;
            bh[2][0] = wreg[kt][1].x; bh[2][1] = wreg[kt][1].y;
            bh[3][0] = wreg[kt][1].z; bh[3][1] = wreg[kt][1].w;
#pragma unroll
            for (int mi = 0; mi < 2; mi++) {
                u32 ah[4];
                uint4 va = ((const uint4*)(smraw + A_OFF))[(kt * 4 + mq * 2 + mi) * 32 + lane];
                ah[0] = va.x; ah[1] = va.y; ah[2] = va.z; ah[3] = va.w;
#pragma unroll
                for (int nj = 0; nj < 4; nj++)
                    mma16816(d[mi][nj], ah, bh[nj]);
            }
        }

        // ---- epilogue: direct STG.64 from fragments ----
        {
            const int oh = 4 * p + r;
#pragma unroll
            for (int nj = 0; nj < 4; nj++) {
                int co = (nq * 4 + nj) * 4 + t;
                float* orow = out + (((size_t)(b * 64 + co)) * 720 + oh) * 1280
                            + 2 * q0;
#pragma unroll
                for (int mi = 0; mi < 2; mi++) {
                    int q = (mq * 2 + mi) * 16 + g;
                    *(float2*)(orow + 2 * q)      = make_float2(d[mi][nj][0], d[mi][nj][1]);
                    *(float2*)(orow + 2 * q + 16) = make_float2(d[mi][nj][2], d[mi][nj][3]);
                }
            }
        }
    }
}

extern "C" void kernel_launch(void* const* d_in, const int* in_sizes, int n_in,
                              void* d_out, int out_size)
{
    // x: 2*3*720*1280 = 5529600, w: 8*64*3*5*5 = 38400, b: 8*64 = 512
    const float* x = nullptr;
    const float* w = nullptr;
    const float* bb = nullptr;
    for (int i = 0; i < n_in; i++) {
        if (in_sizes[i] == 5529600)     x  = (const float*)d_in[i];
        else if (in_sizes[i] == 38400)  w  = (const float*)d_in[i];
        else if (in_sizes[i] == 512)    bb = (const float*)d_in[i];
    }
    float* out = (float*)d_out;

    cudaFuncSetAttribute(svc8_mma_kernel,
                         cudaFuncAttributeMaxDynamicSharedMemorySize, SMEM_BYTES);

    dim3 grid(10, 15, 8);
    svc8_mma_kernel<<<grid, 256, SMEM_BYTES>>>(x, w, bb, out);
}